// round 12
// baseline (speedup 1.0000x reference)
#include <cuda_runtime.h>
#include <math.h>
#include <stdint.h>

#define TT   1024
#define SSZ  1024
#define BB   4
#define DD   1024
#define HH   16
#define HDD  64
#define FFND 4096
#define MM   (TT*BB)

// ---------------- scratch (device globals; no allocs allowed) ----------------
__device__ uint32_t g_state_t[MM*DD];
__device__ uint32_t g_enc_t[MM*DD];
__device__ uint32_t g_qt[MM*DD];
__device__ uint32_t g_kt[MM*DD];
__device__ uint32_t g_vt[MM*DD];
__device__ uint32_t g_ctx_t[MM*DD];
__device__ float    g_tmp[MM*DD];
__device__ float    g_x1[MM*DD];
__device__ uint32_t g_x1t[MM*DD];
__device__ float    g_x2[MM*DD];
__device__ uint32_t g_x2t[MM*DD];
__device__ uint32_t g_ffn_t[(size_t)MM*FFND];
__device__ float    g_rs_self[MM];
__device__ float    g_rs_enc[MM];
__device__ uint32_t g_wtf[16*1024*1024];

#define WOFF_SAQ  (0*1048576)
#define WOFF_SAK  (1*1048576)
#define WOFF_SAV  (2*1048576)
#define WOFF_SAO  (3*1048576)
#define WOFF_EAQ  (4*1048576)
#define WOFF_EAK  (5*1048576)
#define WOFF_EAV  (6*1048576)
#define WOFF_EAO  (7*1048576)
#define WOFF_FC1  (8*1048576)
#define WOFF_FC2  (12*1048576)

// ---------------- helpers ----------------
__device__ __forceinline__ float block_sum(float v) {
    __shared__ float sh[8];
    __shared__ float res;
    int lane = threadIdx.x & 31, w = threadIdx.x >> 5;
    #pragma unroll
    for (int o = 16; o > 0; o >>= 1) v += __shfl_xor_sync(0xffffffffu, v, o);
    __syncthreads();
    if (lane == 0) sh[w] = v;
    __syncthreads();
    if (threadIdx.x == 0) {
        float t = 0.f;
        #pragma unroll
        for (int i = 0; i < 8; i++) t += sh[i];
        res = t;
    }
    __syncthreads();
    return res;
}

__device__ __forceinline__ uint32_t f2tf32(float x) {
    uint32_t u;
    asm("cvt.rna.tf32.f32 %0, %1;" : "=r"(u) : "f"(x));
    return u;
}

__device__ __forceinline__ void mma_tf32(float* d, const uint32_t* a, uint32_t b0, uint32_t b1) {
    asm volatile(
        "mma.sync.aligned.m16n8k8.row.col.f32.tf32.tf32.f32 "
        "{%0,%1,%2,%3}, {%4,%5,%6,%7}, {%8,%9}, {%0,%1,%2,%3};"
        : "+f"(d[0]), "+f"(d[1]), "+f"(d[2]), "+f"(d[3])
        : "r"(a[0]), "r"(a[1]), "r"(a[2]), "r"(a[3]), "r"(b0), "r"(b1));
}

__global__ void expand_mask_kernel(const int* __restrict__ mask,
                                   float* __restrict__ rowscale, int L) {
    int r = blockIdx.x * blockDim.x + threadIdx.x;
    if (r < L * BB) {
        int pos = r / BB, b = r % BB;
        rowscale[r] = mask[b * L + pos] ? 0.f : 1.f;
    }
}

// ---------------- fused fp32 -> tf32 conversion over 12 segments ----------------
struct CvtJobs {
    const float* src[12];
    uint32_t*    dst[12];
    int          n[12];
};

__global__ __launch_bounds__(256) void cvt_all_kernel(CvtJobs jobs)
{
    int seg = blockIdx.y;
    int n = jobs.n[seg];
    int i = (blockIdx.x * blockDim.x + threadIdx.x) * 4;
    if (i < n) {
        float4 v = *(const float4*)(jobs.src[seg] + i);
        uint4 o;
        o.x = f2tf32(v.x); o.y = f2tf32(v.y);
        o.z = f2tf32(v.z); o.w = f2tf32(v.w);
        *(uint4*)(jobs.dst[seg] + i) = o;
    }
}

// =====================================================================
// TF32 GEMM (mma.sync): C[M,N] = A[M,K] @ W[N,K]^T (+bias, rowscale, relu).
// CTA tile 256x128x32, 512 thr (16 warps, 4m x 4n, warp tile 64x32).
// 2-stage cp.async pipeline, SKEW-36 smem. smem = 110592 B.
// =====================================================================
#define SKEW 36
#define A_W  (256*SKEW)
#define B_W  (128*SKEW)
#define STG_W (A_W + B_W)
#define GSMB (2*STG_W*4)

__global__ __launch_bounds__(512) void gemm_tf32_kernel(
    const uint32_t* __restrict__ A, const uint32_t* __restrict__ W,
    const float* __restrict__ bias, const float* __restrict__ rowscale,
    float* __restrict__ C, uint32_t* __restrict__ Ct,
    int M, int N, int K, int relu)
{
    extern __shared__ uint32_t sm[];
    const int tid = threadIdx.x;
    const int lane = tid & 31, warp = tid >> 5;
    const int wm = warp & 3, wn = warp >> 2;      // 4m x 4n
    const int g = lane >> 2, tig = lane & 3;
    const int bx = blockIdx.x, by = blockIdx.y;

    float d[4][4][4];
    #pragma unroll
    for (int mt = 0; mt < 4; mt++)
        #pragma unroll
        for (int nt = 0; nt < 4; nt++)
            #pragma unroll
            for (int i = 0; i < 4; i++) d[mt][nt][i] = 0.f;

    uint32_t smbase = (uint32_t)__cvta_generic_to_shared(sm);
    // A tile: 256 rows x 8 chunks = 2048 / 512 thr = 4 per thread; B: 1024 / 512 = 2
    uint32_t dstA[4], dstB[2];
    const uint32_t *aS[4], *wS[2];
    #pragma unroll
    for (int i = 0; i < 4; i++) {
        int f = tid + (i << 9);
        int r = f >> 3, c4 = (f & 7) << 2;
        dstA[i] = (uint32_t)(r * SKEW + c4) * 4;
        aS[i] = A + (size_t)(by * 256 + r) * K + c4;
    }
    #pragma unroll
    for (int i = 0; i < 2; i++) {
        int f = tid + (i << 9);
        int r = f >> 3, c4 = (f & 7) << 2;
        dstB[i] = (uint32_t)(A_W + r * SKEW + c4) * 4;
        wS[i] = W + (size_t)(bx * 128 + r) * K + c4;
    }

    auto issue = [&](int k0, int stg) {
        uint32_t b = smbase + (uint32_t)stg * (STG_W * 4);
        #pragma unroll
        for (int i = 0; i < 4; i++)
            asm volatile("cp.async.cg.shared.global [%0], [%1], 16;"
                         :: "r"(b + dstA[i]), "l"(aS[i] + k0) : "memory");
        #pragma unroll
        for (int i = 0; i < 2; i++)
            asm volatile("cp.async.cg.shared.global [%0], [%1], 16;"
                         :: "r"(b + dstB[i]), "l"(wS[i] + k0) : "memory");
        asm volatile("cp.async.commit_group;" ::: "memory");
    };

    const int arBase = wm * 64 + g;
    const int bcBase = wn * 32 + g;

    issue(0, 0);
    int stage = 0;
    for (int k0 = 0; k0 < K; k0 += 32) {
        bool nxt = (k0 + 32) < K;
        if (nxt) {
            issue(k0 + 32, stage ^ 1);
            asm volatile("cp.async.wait_group 1;" ::: "memory");
        } else {
            asm volatile("cp.async.wait_group 0;" ::: "memory");
        }
        __syncthreads();

        const uint32_t* Ab = sm + stage * STG_W;
        const uint32_t* Wb = Ab + A_W;
        #pragma unroll
        for (int ks = 0; ks < 4; ks++) {
            int kb = ks * 8;
            uint32_t af[4][4];
            #pragma unroll
            for (int mt = 0; mt < 4; mt++) {
                int ar = arBase + mt * 16;
                af[mt][0] = Ab[ar * SKEW + kb + tig];
                af[mt][1] = Ab[(ar + 8) * SKEW + kb + tig];
                af[mt][2] = Ab[ar * SKEW + kb + tig + 4];
                af[mt][3] = Ab[(ar + 8) * SKEW + kb + tig + 4];
            }
            #pragma unroll
            for (int nt = 0; nt < 4; nt++) {
                int bc = bcBase + nt * 8;
                uint32_t b0 = Wb[bc * SKEW + kb + tig];
                uint32_t b1 = Wb[bc * SKEW + kb + tig + 4];
                #pragma unroll
                for (int mt = 0; mt < 4; mt++)
                    mma_tf32(d[mt][nt], af[mt], b0, b1);
            }
        }
        __syncthreads();
        stage ^= 1;
    }

    #pragma unroll
    for (int mt = 0; mt < 4; mt++) {
        int row0 = by * 256 + wm * 64 + mt * 16 + g;
        float rs0 = rowscale ? rowscale[row0] : 1.f;
        float rs1 = rowscale ? rowscale[row0 + 8] : 1.f;
        #pragma unroll
        for (int nt = 0; nt < 4; nt++) {
            int col = bx * 128 + wn * 32 + nt * 8 + tig * 2;
            float b0 = bias[col], b1 = bias[col + 1];
            float v00 = d[mt][nt][0] * rs0 + b0, v01 = d[mt][nt][1] * rs0 + b1;
            float v10 = d[mt][nt][2] * rs1 + b0, v11 = d[mt][nt][3] * rs1 + b1;
            if (relu) {
                v00 = fmaxf(v00, 0.f); v01 = fmaxf(v01, 0.f);
                v10 = fmaxf(v10, 0.f); v11 = fmaxf(v11, 0.f);
            }
            size_t o0 = (size_t)row0 * N + col;
            size_t o1 = (size_t)(row0 + 8) * N + col;
            if (C) {
                *(float2*)(C + o0) = make_float2(v00, v01);
                *(float2*)(C + o1) = make_float2(v10, v11);
            }
            if (Ct) {
                *(uint2*)(Ct + o0) = make_uint2(f2tf32(v00), f2tf32(v01));
                *(uint2*)(Ct + o1) = make_uint2(f2tf32(v10), f2tf32(v11));
            }
        }
    }
}

// =====================================================================
// Fused flash attention (tf32, mma.sync) — unchanged.
// =====================================================================
#define FQ 0
#define FK 8192
#define FV 16384
#define FP 26624
#define FL_SMEM_WORDS 43008

__global__ __launch_bounds__(256) void flash_tf32_kernel(
    const uint32_t* __restrict__ Q, const uint32_t* __restrict__ Kk,
    const uint32_t* __restrict__ V, const float* __restrict__ mask,
    uint32_t* __restrict__ ctx_t, float* __restrict__ attn, int causal)
{
    extern __shared__ uint32_t sm[];
    uint32_t* Qs = sm + FQ;
    uint32_t* Ks = sm + FK;
    uint32_t* Vs = sm + FV;
    const int tid = threadIdx.x;
    const int lane = tid & 31, warp = tid >> 5;
    const int g = lane >> 2, tig = lane & 3;
    const int bh = blockIdx.y;
    const int b = bh / HH, h = bh % HH;
    const int t0 = blockIdx.x * 128;
    const int wr0 = warp * 16;
    uint32_t* Pw = sm + FP + warp * 2048;

    #pragma unroll
    for (int i = 0; i < 8; i++) {
        int f = tid + (i << 8);
        int r = f >> 4;
        int c4 = (f & 15) << 2;
        int bse = ((c4 >> 3) << 10) + (r << 3) + ((c4 >> 2) & 1);
        uint4 q4 = *(const uint4*)(Q + ((size_t)(t0 + r) * BB + b) * DD + h * HDD + c4);
        Qs[bse + 0] = q4.x; Qs[bse + 2] = q4.y;
        Qs[bse + 4] = q4.z; Qs[bse + 6] = q4.w;
    }

    float mA = -1e30f, mB = -1e30f, lA = 0.f, lB = 0.f;
    float o[8][4];
    #pragma unroll
    for (int nt = 0; nt < 8; nt++)
        #pragma unroll
        for (int i = 0; i < 4; i++) o[nt][i] = 0.f;

    const int pe = ((tig * 2) & 3) * 2 + (tig >> 1);
    const int n_stiles = causal ? (blockIdx.x + 1) : (SSZ / 128);

    for (int is = 0; is < n_stiles; is++) {
        int s0 = is * 128;
        __syncthreads();

        #pragma unroll
        for (int i = 0; i < 8; i++) {
            int f = tid + (i << 8);
            int r = f >> 4;
            int c4 = (f & 15) << 2;
            int bse = ((c4 >> 3) << 10) + (r << 3) + ((c4 >> 2) & 1);
            uint4 k4 = *(const uint4*)(Kk + ((size_t)(s0 + r) * BB + b) * DD + h * HDD + c4);
            Ks[bse + 0] = k4.x; Ks[bse + 2] = k4.y;
            Ks[bse + 4] = k4.z; Ks[bse + 6] = k4.w;
            uint4 v4 = *(const uint4*)(V + ((size_t)(s0 + r) * BB + b) * DD + h * HDD + c4);
            int vb = ((r >> 3) * 640) + ((r & 3) << 1) + ((r >> 2) & 1);
            Vs[vb + (c4 + 0) * 10] = v4.x;
            Vs[vb + (c4 + 1) * 10] = v4.y;
            Vs[vb + (c4 + 2) * 10] = v4.z;
            Vs[vb + (c4 + 3) * 10] = v4.w;
        }
        __syncthreads();

        float s[16][4];
        #pragma unroll
        for (int nt = 0; nt < 16; nt++)
            #pragma unroll
            for (int i = 0; i < 4; i++) s[nt][i] = 0.f;

        #pragma unroll
        for (int ks = 0; ks < 8; ks++) {
            int ab = ks << 10;
            uint2 a0 = *(const uint2*)&Qs[ab + (wr0 + g) * 8 + tig * 2];
            uint2 a1 = *(const uint2*)&Qs[ab + (wr0 + 8 + g) * 8 + tig * 2];
            uint32_t af[4] = {a0.x, a1.x, a0.y, a1.y};
            #pragma unroll
            for (int nt = 0; nt < 16; nt++) {
                uint2 bb = *(const uint2*)&Ks[ab + (nt * 8 + g) * 8 + tig * 2];
                mma_tf32(s[nt], af, bb.x, bb.y);
            }
        }

        const float scale = 0.125f;
        if (causal && is == blockIdx.x) {
            int tAr = t0 + wr0 + g, tBr = tAr + 8;
            #pragma unroll
            for (int nt = 0; nt < 16; nt++) {
                int c = s0 + nt * 8 + tig * 2;
                s[nt][0] = s[nt][0] * scale + mask[(size_t)tAr * TT + c];
                s[nt][1] = s[nt][1] * scale + mask[(size_t)tAr * TT + c + 1];
                s[nt][2] = s[nt][2] * scale + mask[(size_t)tBr * TT + c];
                s[nt][3] = s[nt][3] * scale + mask[(size_t)tBr * TT + c + 1];
            }
        } else {
            #pragma unroll
            for (int nt = 0; nt < 16; nt++)
                #pragma unroll
                for (int i = 0; i < 4; i++) s[nt][i] *= scale;
        }

        float mtA = -1e30f, mtB = -1e30f;
        #pragma unroll
        for (int nt = 0; nt < 16; nt++) {
            mtA = fmaxf(mtA, fmaxf(s[nt][0], s[nt][1]));
            mtB = fmaxf(mtB, fmaxf(s[nt][2], s[nt][3]));
        }
        mtA = fmaxf(mtA, __shfl_xor_sync(0xffffffffu, mtA, 1));
        mtA = fmaxf(mtA, __shfl_xor_sync(0xffffffffu, mtA, 2));
        mtB = fmaxf(mtB, __shfl_xor_sync(0xffffffffu, mtB, 1));
        mtB = fmaxf(mtB, __shfl_xor_sync(0xffffffffu, mtB, 2));

        float mnA = fmaxf(mA, mtA), mnB = fmaxf(mB, mtB);
        float alA = __expf(mA - mnA), alB = __expf(mB - mnB);
        float rsA = 0.f, rsB = 0.f;
        #pragma unroll
        for (int nt = 0; nt < 16; nt++) {
            s[nt][0] = __expf(s[nt][0] - mnA);
            s[nt][1] = __expf(s[nt][1] - mnA);
            s[nt][2] = __expf(s[nt][2] - mnB);
            s[nt][3] = __expf(s[nt][3] - mnB);
            rsA += s[nt][0] + s[nt][1];
            rsB += s[nt][2] + s[nt][3];
        }
        rsA += __shfl_xor_sync(0xffffffffu, rsA, 1);
        rsA += __shfl_xor_sync(0xffffffffu, rsA, 2);
        rsB += __shfl_xor_sync(0xffffffffu, rsB, 1);
        rsB += __shfl_xor_sync(0xffffffffu, rsB, 2);
        lA = lA * alA + rsA; mA = mnA;
        lB = lB * alB + rsB; mB = mnB;

        #pragma unroll
        for (int nt = 0; nt < 8; nt++) {
            o[nt][0] *= alA; o[nt][1] *= alA;
            o[nt][2] *= alB; o[nt][3] *= alB;
        }

        __syncwarp();
        #pragma unroll
        for (int nt = 0; nt < 16; nt++) {
            int base = (nt << 7) + g * 8 + pe;
            Pw[base]          = f2tf32(s[nt][0]);
            Pw[base + 2]      = f2tf32(s[nt][1]);
            Pw[base + 64]     = f2tf32(s[nt][2]);
            Pw[base + 64 + 2] = f2tf32(s[nt][3]);
        }
        __syncwarp();

        #pragma unroll
        for (int ks = 0; ks < 16; ks++) {
            uint2 a0 = *(const uint2*)&Pw[(ks << 7) + g * 8 + tig * 2];
            uint2 a1 = *(const uint2*)&Pw[(ks << 7) + (g + 8) * 8 + tig * 2];
            uint32_t af[4] = {a0.x, a1.x, a0.y, a1.y};
            #pragma unroll
            for (int nt = 0; nt < 8; nt++) {
                uint2 bb = *(const uint2*)&Vs[ks * 640 + (nt * 8 + g) * 10 + tig * 2];
                mma_tf32(o[nt], af, bb.x, bb.y);
            }
        }
    }

    float invA = 1.f / lA, invB = 1.f / lB;
    int tA = t0 + wr0 + g, tB = tA + 8;
    #pragma unroll
    for (int nt = 0; nt < 8; nt++) {
        int hd = nt * 8 + tig * 2;
        float a0 = o[nt][0] * invA, a1 = o[nt][1] * invA;
        float b0 = o[nt][2] * invB, b1 = o[nt][3] * invB;
        *(uint2*)(ctx_t + ((size_t)tA * BB + b) * DD + h * HDD + hd) = make_uint2(f2tf32(a0), f2tf32(a1));
        *(uint2*)(ctx_t + ((size_t)tB * BB + b) * DD + h * HDD + hd) = make_uint2(f2tf32(b0), f2tf32(b1));
        if (attn) {
            *(float2*)(attn + (((size_t)h * BB + b) * TT + tA) * HDD + hd) = make_float2(a0, a1);
            *(float2*)(attn + (((size_t)h * BB + b) * TT + tB) * HDD + hd) = make_float2(b0, b1);
        }
    }
}

// ---------------- fused residual add + layernorm (optional tf32 dual store)
__global__ __launch_bounds__(256) void add_ln_kernel(
    const float* __restrict__ a, const float* __restrict__ r,
    const float* __restrict__ g, const float* __restrict__ be,
    float* __restrict__ o, uint32_t* __restrict__ ot)
{
    size_t row = blockIdx.x;
    int tid = threadIdx.x;
    float4 va = *(const float4*)(a + row * DD + tid * 4);
    float4 vr = *(const float4*)(r + row * DD + tid * 4);
    float x0 = va.x + vr.x, x1 = va.y + vr.y, x2 = va.z + vr.z, x3 = va.w + vr.w;
    float s  = block_sum(x0 + x1 + x2 + x3);
    float mu = s * (1.f / DD);
    float d0 = x0 - mu, d1 = x1 - mu, d2 = x2 - mu, d3 = x3 - mu;
    float sq = block_sum(d0 * d0 + d1 * d1 + d2 * d2 + d3 * d3);
    float inv = rsqrtf(sq * (1.f / DD) + 1e-5f);
    float4 vg = *(const float4*)(g + tid * 4);
    float4 vb = *(const float4*)(be + tid * 4);
    float4 out;
    out.x = d0 * inv * vg.x + vb.x;
    out.y = d1 * inv * vg.y + vb.y;
    out.z = d2 * inv * vg.z + vb.z;
    out.w = d3 * inv * vg.w + vb.w;
    *(float4*)(o + row * DD + tid * 4) = out;
    if (ot) {
        uint4 t;
        t.x = f2tf32(out.x); t.y = f2tf32(out.y);
        t.z = f2tf32(out.z); t.w = f2tf32(out.w);
        *(uint4*)(ot + row * DD + tid * 4) = t;
    }
}

// ---------------- host launch ----------------
extern "C" void kernel_launch(void* const* d_in, const int* in_sizes, int n_in,
                              void* d_out, int out_size)
{
    const float* state = (const float*)d_in[0];
    const float* enc   = (const float*)d_in[1];
    const float* amask = (const float*)d_in[2];
    const int* spad = (const int*)d_in[3];
    const int* epad = (const int*)d_in[4];
    const float *saWq = (const float*)d_in[5],  *sabq = (const float*)d_in[6];
    const float *saWk = (const float*)d_in[7],  *sabk = (const float*)d_in[8];
    const float *saWv = (const float*)d_in[9],  *sabv = (const float*)d_in[10];
    const float *saWo = (const float*)d_in[11], *sabo = (const float*)d_in[12];
    const float *eaWq = (const float*)d_in[13], *eabq = (const float*)d_in[14];
    const float *eaWk = (const float*)d_in[15], *eabk = (const float*)d_in[16];
    const float *eaWv = (const float*)d_in[17], *eabv = (const float*)d_in[18];
    const float *eaWo = (const float*)d_in[19], *eabo = (const float*)d_in[20];
    const float *ln1g = (const float*)d_in[21], *ln1b = (const float*)d_in[22];
    const float *ln2g = (const float*)d_in[23], *ln2b = (const float*)d_in[24];
    const float *ln3g = (const float*)d_in[25], *ln3b = (const float*)d_in[26];
    const float *fc1W = (const float*)d_in[27], *fc1b = (const float*)d_in[28];
    const float *fc2W = (const float*)d_in[29], *fc2b = (const float*)d_in[30];

    uint32_t *state_t, *enc_t, *qt, *kt, *vt, *ctx_t, *x1t, *x2t, *ffn_t, *wtf;
    float *tmp, *x1, *x2, *rss, *rse;
    cudaGetSymbolAddress((void**)&state_t, g_state_t);
    cudaGetSymbolAddress((void**)&enc_t,   g_enc_t);
    cudaGetSymbolAddress((void**)&qt,  g_qt);
    cudaGetSymbolAddress((void**)&kt,  g_kt);
    cudaGetSymbolAddress((void**)&vt,  g_vt);
    cudaGetSymbolAddress((void**)&ctx_t, g_ctx_t);
    cudaGetSymbolAddress((void**)&tmp, g_tmp);
    cudaGetSymbolAddress((void**)&x1,  g_x1);
    cudaGetSymbolAddress((void**)&x1t, g_x1t);
    cudaGetSymbolAddress((void**)&x2,  g_x2);
    cudaGetSymbolAddress((void**)&x2t, g_x2t);
    cudaGetSymbolAddress((void**)&ffn_t, g_ffn_t);
    cudaGetSymbolAddress((void**)&rss, g_rs_self);
    cudaGetSymbolAddress((void**)&rse, g_rs_enc);
    cudaGetSymbolAddress((void**)&wtf, g_wtf);

    const int FSM = FL_SMEM_WORDS * 4;
    cudaFuncSetAttribute(gemm_tf32_kernel,  cudaFuncAttributeMaxDynamicSharedMemorySize, GSMB);
    cudaFuncSetAttribute(flash_tf32_kernel, cudaFuncAttributeMaxDynamicSharedMemorySize, FSM);

    float* outx = (float*)d_out;
    float* outa = outx + (size_t)MM * DD;

    // ---- pre-convert weights + input activations (one fused kernel) ----
    const int NW = DD * DD;
    const int NF = FFND * DD;
    const int NA = MM * DD;
    CvtJobs jobs;
    jobs.src[0] = saWq; jobs.dst[0] = wtf + WOFF_SAQ; jobs.n[0] = NW;
    jobs.src[1] = saWk; jobs.dst[1] = wtf + WOFF_SAK; jobs.n[1] = NW;
    jobs.src[2] = saWv; jobs.dst[2] = wtf + WOFF_SAV; jobs.n[2] = NW;
    jobs.src[3] = saWo; jobs.dst[3] = wtf + WOFF_SAO; jobs.n[3] = NW;
    jobs.src[4] = eaWq; jobs.dst[4] = wtf + WOFF_EAQ; jobs.n[4] = NW;
    jobs.src[5] = eaWk; jobs.dst[5] = wtf + WOFF_EAK; jobs.n[5] = NW;
    jobs.src[6] = eaWv; jobs.dst[6] = wtf + WOFF_EAV; jobs.n[6] = NW;
    jobs.src[7] = eaWo; jobs.dst[7] = wtf + WOFF_EAO; jobs.n[7] = NW;
    jobs.src[8] = fc1W; jobs.dst[8] = wtf + WOFF_FC1; jobs.n[8] = NF;
    jobs.src[9] = fc2W; jobs.dst[9] = wtf + WOFF_FC2; jobs.n[9] = NF;
    jobs.src[10] = state; jobs.dst[10] = state_t; jobs.n[10] = NA;
    jobs.src[11] = enc;   jobs.dst[11] = enc_t;   jobs.n[11] = NA;
    cvt_all_kernel<<<dim3(NF / 1024, 12), 256>>>(jobs);

    expand_mask_kernel<<<(MM + 255) / 256, 256>>>(spad, rss, TT);
    expand_mask_kernel<<<(MM + 255) / 256, 256>>>(epad, rse, SSZ);

    dim3 gP(DD / 128, MM / 256);        // 128 CTAs
    dim3 gF1(FFND / 128, MM / 256);
    dim3 gFl(TT / 128, BB * HH);

    // ---- self-attention ----
    gemm_tf32_kernel<<<gP, 512, GSMB>>>(state_t, wtf + WOFF_SAQ, sabq, nullptr, nullptr, qt, MM, DD, DD, 0);
    gemm_tf32_kernel<<<gP, 512, GSMB>>>(state_t, wtf + WOFF_SAK, sabk, rss,     nullptr, kt, MM, DD, DD, 0);
    gemm_tf32_kernel<<<gP, 512, GSMB>>>(state_t, wtf + WOFF_SAV, sabv, nullptr, nullptr, vt, MM, DD, DD, 0);
    flash_tf32_kernel<<<gFl, 256, FSM>>>(qt, kt, vt, amask, ctx_t, nullptr, 1);
    gemm_tf32_kernel<<<gP, 512, GSMB>>>(ctx_t, wtf + WOFF_SAO, sabo, nullptr, tmp, nullptr, MM, DD, DD, 0);
    add_ln_kernel<<<MM, 256>>>(tmp, state, ln1g, ln1b, x1, x1t);

    // ---- encoder-decoder attention ----
    gemm_tf32_kernel<<<gP, 512, GSMB>>>(x1t,   wtf + WOFF_EAQ, eabq, nullptr, nullptr, qt, MM, DD, DD, 0);
    gemm_tf32_kernel<<<gP, 512, GSMB>>>(enc_t, wtf + WOFF_EAK, eabk, rse,     nullptr, kt, MM, DD, DD, 0);
    gemm_tf32_kernel<<<gP, 512, GSMB>>>(enc_t, wtf + WOFF_EAV, eabv, nullptr, nullptr, vt, MM, DD, DD, 0);
    flash_tf32_kernel<<<gFl, 256, FSM>>>(qt, kt, vt, nullptr, ctx_t, outa, 0);
    gemm_tf32_kernel<<<gP, 512, GSMB>>>(ctx_t, wtf + WOFF_EAO, eabo, nullptr, tmp, nullptr, MM, DD, DD, 0);
    add_ln_kernel<<<MM, 256>>>(tmp, x1, ln2g, ln2b, x2, x2t);

    // ---- FFN ----
    gemm_tf32_kernel<<<gF1, 512, GSMB>>>(x2t,   wtf + WOFF_FC1, fc1b, nullptr, nullptr, ffn_t, MM, FFND, DD, 1);
    gemm_tf32_kernel<<<gP, 512, GSMB>>>(ffn_t, wtf + WOFF_FC2, fc2b, nullptr, tmp, nullptr, MM, DD, FFND, 0);
    add_ln_kernel<<<MM, 256>>>(tmp, x2, ln3g, ln3b, outx, nullptr);
}

// round 13
// speedup vs baseline: 1.5428x; 1.5428x over previous
#include <cuda_runtime.h>
#include <cuda_fp16.h>
#include <math.h>
#include <stdint.h>

#define TT   1024
#define SSZ  1024
#define BB   4
#define DD   1024
#define HH   16
#define HDD  64
#define FFND 4096
#define MM   (TT*BB)

// ---------------- scratch (device globals; no allocs allowed) ----------------
__device__ __half   g_state_h[MM*DD];
__device__ __half   g_enc_h[MM*DD];
__device__ uint32_t g_qt[MM*DD];          // tf32 for flash
__device__ uint32_t g_kt[MM*DD];
__device__ uint32_t g_vt[MM*DD];
__device__ __half   g_ctx_h[MM*DD];
__device__ float    g_tmp[MM*DD];
__device__ float    g_x1[MM*DD];
__device__ __half   g_x1h[MM*DD];
__device__ float    g_x2[MM*DD];
__device__ __half   g_x2h[MM*DD];
__device__ __half   g_ffn_h[(size_t)MM*FFND];
__device__ float    g_rs_self[MM];
__device__ float    g_rs_enc[MM];
__device__ __half   g_wh[16*1024*1024];   // fp16 weights (32MB)

#define WOFF_SAQ  (0*1048576)
#define WOFF_SAK  (1*1048576)
#define WOFF_SAV  (2*1048576)
#define WOFF_SAO  (3*1048576)
#define WOFF_EAQ  (4*1048576)
#define WOFF_EAK  (5*1048576)
#define WOFF_EAV  (6*1048576)
#define WOFF_EAO  (7*1048576)
#define WOFF_FC1  (8*1048576)
#define WOFF_FC2  (12*1048576)

// ---------------- helpers ----------------
__device__ __forceinline__ float block_sum(float v) {
    __shared__ float sh[8];
    __shared__ float res;
    int lane = threadIdx.x & 31, w = threadIdx.x >> 5;
    #pragma unroll
    for (int o = 16; o > 0; o >>= 1) v += __shfl_xor_sync(0xffffffffu, v, o);
    __syncthreads();
    if (lane == 0) sh[w] = v;
    __syncthreads();
    if (threadIdx.x == 0) {
        float t = 0.f;
        #pragma unroll
        for (int i = 0; i < 8; i++) t += sh[i];
        res = t;
    }
    __syncthreads();
    return res;
}

__device__ __forceinline__ uint32_t f2tf32(float x) {
    uint32_t u;
    asm("cvt.rna.tf32.f32 %0, %1;" : "=r"(u) : "f"(x));
    return u;
}

__device__ __forceinline__ void mma_tf32(float* d, const uint32_t* a, uint32_t b0, uint32_t b1) {
    asm volatile(
        "mma.sync.aligned.m16n8k8.row.col.f32.tf32.tf32.f32 "
        "{%0,%1,%2,%3}, {%4,%5,%6,%7}, {%8,%9}, {%0,%1,%2,%3};"
        : "+f"(d[0]), "+f"(d[1]), "+f"(d[2]), "+f"(d[3])
        : "r"(a[0]), "r"(a[1]), "r"(a[2]), "r"(a[3]), "r"(b0), "r"(b1));
}

__device__ __forceinline__ void mma_fp16(float* d, const uint32_t* a, uint32_t b0, uint32_t b1) {
    asm volatile(
        "mma.sync.aligned.m16n8k16.row.col.f32.f16.f16.f32 "
        "{%0,%1,%2,%3}, {%4,%5,%6,%7}, {%8,%9}, {%0,%1,%2,%3};"
        : "+f"(d[0]), "+f"(d[1]), "+f"(d[2]), "+f"(d[3])
        : "r"(a[0]), "r"(a[1]), "r"(a[2]), "r"(a[3]), "r"(b0), "r"(b1));
}

__global__ void expand_mask_kernel(const int* __restrict__ mask,
                                   float* __restrict__ rowscale, int L) {
    int r = blockIdx.x * blockDim.x + threadIdx.x;
    if (r < L * BB) {
        int pos = r / BB, b = r % BB;
        rowscale[r] = mask[b * L + pos] ? 0.f : 1.f;
    }
}

// ---------------- fused fp32 -> fp16 conversion over 12 segments ----------------
struct CvtJobs {
    const float* src[12];
    __half*      dst[12];
    int          n[12];
};

__global__ __launch_bounds__(256) void cvt_all_kernel(CvtJobs jobs)
{
    int seg = blockIdx.y;
    int n = jobs.n[seg];
    int i = (blockIdx.x * blockDim.x + threadIdx.x) * 4;
    if (i < n) {
        float4 v = *(const float4*)(jobs.src[seg] + i);
        __half2 h0 = __floats2half2_rn(v.x, v.y);
        __half2 h1 = __floats2half2_rn(v.z, v.w);
        *(__half2*)(jobs.dst[seg] + i)     = h0;
        *(__half2*)(jobs.dst[seg] + i + 2) = h1;
    }
}

// =====================================================================
// FP16 GEMM (mma.m16n8k16): C = A[M,K] @ W[N,K]^T (+bias, rowscale, relu).
// CTA 256x128, K-chunk 64 halfs (128B/row). 256 thr, 8 warps 4m x 2n,
// warp tile 64x64. 2-stage cp.async, SKEW-36-word smem rows (32 data words).
// outputs: C (fp32), Ct32 (tf32 words, for flash), Ct16 (fp16, next GEMM).
// =====================================================================
#define SKEW 36
#define A_W  (256*SKEW)
#define B_W  (128*SKEW)
#define STG_W (A_W + B_W)
#define GSMB (2*STG_W*4)

__global__ __launch_bounds__(256) void gemm_fp16_kernel(
    const __half* __restrict__ A, const __half* __restrict__ W,
    const float* __restrict__ bias, const float* __restrict__ rowscale,
    float* __restrict__ C, uint32_t* __restrict__ Ct32, __half* __restrict__ Ct16,
    int M, int N, int K, int relu)
{
    extern __shared__ uint32_t sm[];
    const int tid = threadIdx.x;
    const int lane = tid & 31, warp = tid >> 5;
    const int wm = warp & 3, wn = warp >> 2;
    const int g = lane >> 2, tig = lane & 3;
    const int bx = blockIdx.x, by = blockIdx.y;

    float d[4][8][4];
    #pragma unroll
    for (int mt = 0; mt < 4; mt++)
        #pragma unroll
        for (int nt = 0; nt < 8; nt++)
            #pragma unroll
            for (int i = 0; i < 4; i++) d[mt][nt][i] = 0.f;

    uint32_t smbase = (uint32_t)__cvta_generic_to_shared(sm);
    // A: 256 rows x 8 16B-chunks (8 halfs each) = 2048 -> 8/thread; B: 1024 -> 4/thread
    uint32_t dstA[8], dstB[4];
    const __half *aS[8], *wS[4];
    #pragma unroll
    for (int i = 0; i < 8; i++) {
        int f = tid + (i << 8);
        int r = f >> 3, c16 = f & 7;
        dstA[i] = (uint32_t)(r * SKEW + c16 * 4) * 4;
        aS[i] = A + (size_t)(by * 256 + r) * K + c16 * 8;
    }
    #pragma unroll
    for (int i = 0; i < 4; i++) {
        int f = tid + (i << 8);
        int r = f >> 3, c16 = f & 7;
        dstB[i] = (uint32_t)(A_W + r * SKEW + c16 * 4) * 4;
        wS[i] = W + (size_t)(bx * 128 + r) * K + c16 * 8;
    }

    auto issue = [&](int k0, int stg) {
        uint32_t b = smbase + (uint32_t)stg * (STG_W * 4);
        #pragma unroll
        for (int i = 0; i < 8; i++)
            asm volatile("cp.async.cg.shared.global [%0], [%1], 16;"
                         :: "r"(b + dstA[i]), "l"(aS[i] + k0) : "memory");
        #pragma unroll
        for (int i = 0; i < 4; i++)
            asm volatile("cp.async.cg.shared.global [%0], [%1], 16;"
                         :: "r"(b + dstB[i]), "l"(wS[i] + k0) : "memory");
        asm volatile("cp.async.commit_group;" ::: "memory");
    };

    const int arBase = wm * 64 + g;
    const int bcBase = wn * 64 + g;

    issue(0, 0);
    int stage = 0;
    for (int k0 = 0; k0 < K; k0 += 64) {
        bool nxt = (k0 + 64) < K;
        if (nxt) {
            issue(k0 + 64, stage ^ 1);
            asm volatile("cp.async.wait_group 1;" ::: "memory");
        } else {
            asm volatile("cp.async.wait_group 0;" ::: "memory");
        }
        __syncthreads();

        const uint32_t* Ab = sm + stage * STG_W;
        const uint32_t* Wb = Ab + A_W;
        #pragma unroll
        for (int ks = 0; ks < 4; ks++) {          // each ks = k16 halfs = 8 words
            int kb = ks * 8;
            uint32_t af[4][4];
            #pragma unroll
            for (int mt = 0; mt < 4; mt++) {
                int ar = arBase + mt * 16;
                af[mt][0] = Ab[ar * SKEW + kb + tig];
                af[mt][1] = Ab[(ar + 8) * SKEW + kb + tig];
                af[mt][2] = Ab[ar * SKEW + kb + tig + 4];
                af[mt][3] = Ab[(ar + 8) * SKEW + kb + tig + 4];
            }
            #pragma unroll
            for (int nt = 0; nt < 8; nt++) {
                int bc = bcBase + nt * 8;
                uint32_t b0 = Wb[bc * SKEW + kb + tig];
                uint32_t b1 = Wb[bc * SKEW + kb + tig + 4];
                #pragma unroll
                for (int mt = 0; mt < 4; mt++)
                    mma_fp16(d[mt][nt], af[mt], b0, b1);
            }
        }
        __syncthreads();
        stage ^= 1;
    }

    #pragma unroll
    for (int mt = 0; mt < 4; mt++) {
        int row0 = by * 256 + wm * 64 + mt * 16 + g;
        float rs0 = rowscale ? rowscale[row0] : 1.f;
        float rs1 = rowscale ? rowscale[row0 + 8] : 1.f;
        #pragma unroll
        for (int nt = 0; nt < 8; nt++) {
            int col = bx * 128 + wn * 64 + nt * 8 + tig * 2;
            float b0 = bias[col], b1 = bias[col + 1];
            float v00 = d[mt][nt][0] * rs0 + b0, v01 = d[mt][nt][1] * rs0 + b1;
            float v10 = d[mt][nt][2] * rs1 + b0, v11 = d[mt][nt][3] * rs1 + b1;
            if (relu) {
                v00 = fmaxf(v00, 0.f); v01 = fmaxf(v01, 0.f);
                v10 = fmaxf(v10, 0.f); v11 = fmaxf(v11, 0.f);
            }
            size_t o0 = (size_t)row0 * N + col;
            size_t o1 = (size_t)(row0 + 8) * N + col;
            if (C) {
                *(float2*)(C + o0) = make_float2(v00, v01);
                *(float2*)(C + o1) = make_float2(v10, v11);
            }
            if (Ct32) {
                *(uint2*)(Ct32 + o0) = make_uint2(f2tf32(v00), f2tf32(v01));
                *(uint2*)(Ct32 + o1) = make_uint2(f2tf32(v10), f2tf32(v11));
            }
            if (Ct16) {
                *(__half2*)(Ct16 + o0) = __floats2half2_rn(v00, v01);
                *(__half2*)(Ct16 + o1) = __floats2half2_rn(v10, v11);
            }
        }
    }
}

// =====================================================================
// Fused flash attention (tf32 internals, unchanged). Q/K/V tf32 words;
// ctx output fp16, attn output fp32.
// =====================================================================
#define FQ 0
#define FK 8192
#define FV 16384
#define FP 26624
#define FL_SMEM_WORDS 43008

__global__ __launch_bounds__(256) void flash_tf32_kernel(
    const uint32_t* __restrict__ Q, const uint32_t* __restrict__ Kk,
    const uint32_t* __restrict__ V, const float* __restrict__ mask,
    __half* __restrict__ ctx_h, float* __restrict__ attn, int causal)
{
    extern __shared__ uint32_t sm[];
    uint32_t* Qs = sm + FQ;
    uint32_t* Ks = sm + FK;
    uint32_t* Vs = sm + FV;
    const int tid = threadIdx.x;
    const int lane = tid & 31, warp = tid >> 5;
    const int g = lane >> 2, tig = lane & 3;
    const int bh = blockIdx.y;
    const int b = bh / HH, h = bh % HH;
    const int t0 = blockIdx.x * 128;
    const int wr0 = warp * 16;
    uint32_t* Pw = sm + FP + warp * 2048;

    #pragma unroll
    for (int i = 0; i < 8; i++) {
        int f = tid + (i << 8);
        int r = f >> 4;
        int c4 = (f & 15) << 2;
        int bse = ((c4 >> 3) << 10) + (r << 3) + ((c4 >> 2) & 1);
        uint4 q4 = *(const uint4*)(Q + ((size_t)(t0 + r) * BB + b) * DD + h * HDD + c4);
        Qs[bse + 0] = q4.x; Qs[bse + 2] = q4.y;
        Qs[bse + 4] = q4.z; Qs[bse + 6] = q4.w;
    }

    float mA = -1e30f, mB = -1e30f, lA = 0.f, lB = 0.f;
    float o[8][4];
    #pragma unroll
    for (int nt = 0; nt < 8; nt++)
        #pragma unroll
        for (int i = 0; i < 4; i++) o[nt][i] = 0.f;

    const int pe = ((tig * 2) & 3) * 2 + (tig >> 1);
    const int n_stiles = causal ? (blockIdx.x + 1) : (SSZ / 128);

    for (int is = 0; is < n_stiles; is++) {
        int s0 = is * 128;
        __syncthreads();

        #pragma unroll
        for (int i = 0; i < 8; i++) {
            int f = tid + (i << 8);
            int r = f >> 4;
            int c4 = (f & 15) << 2;
            int bse = ((c4 >> 3) << 10) + (r << 3) + ((c4 >> 2) & 1);
            uint4 k4 = *(const uint4*)(Kk + ((size_t)(s0 + r) * BB + b) * DD + h * HDD + c4);
            Ks[bse + 0] = k4.x; Ks[bse + 2] = k4.y;
            Ks[bse + 4] = k4.z; Ks[bse + 6] = k4.w;
            uint4 v4 = *(const uint4*)(V + ((size_t)(s0 + r) * BB + b) * DD + h * HDD + c4);
            int vb = ((r >> 3) * 640) + ((r & 3) << 1) + ((r >> 2) & 1);
            Vs[vb + (c4 + 0) * 10] = v4.x;
            Vs[vb + (c4 + 1) * 10] = v4.y;
            Vs[vb + (c4 + 2) * 10] = v4.z;
            Vs[vb + (c4 + 3) * 10] = v4.w;
        }
        __syncthreads();

        float s[16][4];
        #pragma unroll
        for (int nt = 0; nt < 16; nt++)
            #pragma unroll
            for (int i = 0; i < 4; i++) s[nt][i] = 0.f;

        #pragma unroll
        for (int ks = 0; ks < 8; ks++) {
            int ab = ks << 10;
            uint2 a0 = *(const uint2*)&Qs[ab + (wr0 + g) * 8 + tig * 2];
            uint2 a1 = *(const uint2*)&Qs[ab + (wr0 + 8 + g) * 8 + tig * 2];
            uint32_t af[4] = {a0.x, a1.x, a0.y, a1.y};
            #pragma unroll
            for (int nt = 0; nt < 16; nt++) {
                uint2 bb = *(const uint2*)&Ks[ab + (nt * 8 + g) * 8 + tig * 2];
                mma_tf32(s[nt], af, bb.x, bb.y);
            }
        }

        const float scale = 0.125f;
        if (causal && is == blockIdx.x) {
            int tAr = t0 + wr0 + g, tBr = tAr + 8;
            #pragma unroll
            for (int nt = 0; nt < 16; nt++) {
                int c = s0 + nt * 8 + tig * 2;
                s[nt][0] = s[nt][0] * scale + mask[(size_t)tAr * TT + c];
                s[nt][1] = s[nt][1] * scale + mask[(size_t)tAr * TT + c + 1];
                s[nt][2] = s[nt][2] * scale + mask[(size_t)tBr * TT + c];
                s[nt][3] = s[nt][3] * scale + mask[(size_t)tBr * TT + c + 1];
            }
        } else {
            #pragma unroll
            for (int nt = 0; nt < 16; nt++)
                #pragma unroll
                for (int i = 0; i < 4; i++) s[nt][i] *= scale;
        }

        float mtA = -1e30f, mtB = -1e30f;
        #pragma unroll
        for (int nt = 0; nt < 16; nt++) {
            mtA = fmaxf(mtA, fmaxf(s[nt][0], s[nt][1]));
            mtB = fmaxf(mtB, fmaxf(s[nt][2], s[nt][3]));
        }
        mtA = fmaxf(mtA, __shfl_xor_sync(0xffffffffu, mtA, 1));
        mtA = fmaxf(mtA, __shfl_xor_sync(0xffffffffu, mtA, 2));
        mtB = fmaxf(mtB, __shfl_xor_sync(0xffffffffu, mtB, 1));
        mtB = fmaxf(mtB, __shfl_xor_sync(0xffffffffu, mtB, 2));

        float mnA = fmaxf(mA, mtA), mnB = fmaxf(mB, mtB);
        float alA = __expf(mA - mnA), alB = __expf(mB - mnB);
        float rsA = 0.f, rsB = 0.f;
        #pragma unroll
        for (int nt = 0; nt < 16; nt++) {
            s[nt][0] = __expf(s[nt][0] - mnA);
            s[nt][1] = __expf(s[nt][1] - mnA);
            s[nt][2] = __expf(s[nt][2] - mnB);
            s[nt][3] = __expf(s[nt][3] - mnB);
            rsA += s[nt][0] + s[nt][1];
            rsB += s[nt][2] + s[nt][3];
        }
        rsA += __shfl_xor_sync(0xffffffffu, rsA, 1);
        rsA += __shfl_xor_sync(0xffffffffu, rsA, 2);
        rsB += __shfl_xor_sync(0xffffffffu, rsB, 1);
        rsB += __shfl_xor_sync(0xffffffffu, rsB, 2);
        lA = lA * alA + rsA; mA = mnA;
        lB = lB * alB + rsB; mB = mnB;

        #pragma unroll
        for (int nt = 0; nt < 8; nt++) {
            o[nt][0] *= alA; o[nt][1] *= alA;
            o[nt][2] *= alB; o[nt][3] *= alB;
        }

        __syncwarp();
        #pragma unroll
        for (int nt = 0; nt < 16; nt++) {
            int base = (nt << 7) + g * 8 + pe;
            Pw[base]          = f2tf32(s[nt][0]);
            Pw[base + 2]      = f2tf32(s[nt][1]);
            Pw[base + 64]     = f2tf32(s[nt][2]);
            Pw[base + 64 + 2] = f2tf32(s[nt][3]);
        }
        __syncwarp();

        #pragma unroll
        for (int ks = 0; ks < 16; ks++) {
            uint2 a0 = *(const uint2*)&Pw[(ks << 7) + g * 8 + tig * 2];
            uint2 a1 = *(const uint2*)&Pw[(ks << 7) + (g + 8) * 8 + tig * 2];
            uint32_t af[4] = {a0.x, a1.x, a0.y, a1.y};
            #pragma unroll
            for (int nt = 0; nt < 8; nt++) {
                uint2 bb = *(const uint2*)&Vs[ks * 640 + (nt * 8 + g) * 10 + tig * 2];
                mma_tf32(o[nt], af, bb.x, bb.y);
            }
        }
    }

    float invA = 1.f / lA, invB = 1.f / lB;
    int tA = t0 + wr0 + g, tB = tA + 8;
    #pragma unroll
    for (int nt = 0; nt < 8; nt++) {
        int hd = nt * 8 + tig * 2;
        float a0 = o[nt][0] * invA, a1 = o[nt][1] * invA;
        float b0 = o[nt][2] * invB, b1 = o[nt][3] * invB;
        *(__half2*)(ctx_h + ((size_t)tA * BB + b) * DD + h * HDD + hd) = __floats2half2_rn(a0, a1);
        *(__half2*)(ctx_h + ((size_t)tB * BB + b) * DD + h * HDD + hd) = __floats2half2_rn(b0, b1);
        if (attn) {
            *(float2*)(attn + (((size_t)h * BB + b) * TT + tA) * HDD + hd) = make_float2(a0, a1);
            *(float2*)(attn + (((size_t)h * BB + b) * TT + tB) * HDD + hd) = make_float2(b0, b1);
        }
    }
}

// ---------------- fused residual add + layernorm (optional fp16 dual store)
__global__ __launch_bounds__(256) void add_ln_kernel(
    const float* __restrict__ a, const float* __restrict__ r,
    const float* __restrict__ g, const float* __restrict__ be,
    float* __restrict__ o, __half* __restrict__ oh)
{
    size_t row = blockIdx.x;
    int tid = threadIdx.x;
    float4 va = *(const float4*)(a + row * DD + tid * 4);
    float4 vr = *(const float4*)(r + row * DD + tid * 4);
    float x0 = va.x + vr.x, x1 = va.y + vr.y, x2 = va.z + vr.z, x3 = va.w + vr.w;
    float s  = block_sum(x0 + x1 + x2 + x3);
    float mu = s * (1.f / DD);
    float d0 = x0 - mu, d1 = x1 - mu, d2 = x2 - mu, d3 = x3 - mu;
    float sq = block_sum(d0 * d0 + d1 * d1 + d2 * d2 + d3 * d3);
    float inv = rsqrtf(sq * (1.f / DD) + 1e-5f);
    float4 vg = *(const float4*)(g + tid * 4);
    float4 vb = *(const float4*)(be + tid * 4);
    float4 out;
    out.x = d0 * inv * vg.x + vb.x;
    out.y = d1 * inv * vg.y + vb.y;
    out.z = d2 * inv * vg.z + vb.z;
    out.w = d3 * inv * vg.w + vb.w;
    *(float4*)(o + row * DD + tid * 4) = out;
    if (oh) {
        *(__half2*)(oh + row * DD + tid * 4)     = __floats2half2_rn(out.x, out.y);
        *(__half2*)(oh + row * DD + tid * 4 + 2) = __floats2half2_rn(out.z, out.w);
    }
}

// ---------------- host launch ----------------
extern "C" void kernel_launch(void* const* d_in, const int* in_sizes, int n_in,
                              void* d_out, int out_size)
{
    const float* state = (const float*)d_in[0];
    const float* enc   = (const float*)d_in[1];
    const float* amask = (const float*)d_in[2];
    const int* spad = (const int*)d_in[3];
    const int* epad = (const int*)d_in[4];
    const float *saWq = (const float*)d_in[5],  *sabq = (const float*)d_in[6];
    const float *saWk = (const float*)d_in[7],  *sabk = (const float*)d_in[8];
    const float *saWv = (const float*)d_in[9],  *sabv = (const float*)d_in[10];
    const float *saWo = (const float*)d_in[11], *sabo = (const float*)d_in[12];
    const float *eaWq = (const float*)d_in[13], *eabq = (const float*)d_in[14];
    const float *eaWk = (const float*)d_in[15], *eabk = (const float*)d_in[16];
    const float *eaWv = (const float*)d_in[17], *eabv = (const float*)d_in[18];
    const float *eaWo = (const float*)d_in[19], *eabo = (const float*)d_in[20];
    const float *ln1g = (const float*)d_in[21], *ln1b = (const float*)d_in[22];
    const float *ln2g = (const float*)d_in[23], *ln2b = (const float*)d_in[24];
    const float *ln3g = (const float*)d_in[25], *ln3b = (const float*)d_in[26];
    const float *fc1W = (const float*)d_in[27], *fc1b = (const float*)d_in[28];
    const float *fc2W = (const float*)d_in[29], *fc2b = (const float*)d_in[30];

    __half *state_h, *enc_h, *ctx_h, *x1h, *x2h, *ffn_h, *wh;
    uint32_t *qt, *kt, *vt;
    float *tmp, *x1, *x2, *rss, *rse;
    cudaGetSymbolAddress((void**)&state_h, g_state_h);
    cudaGetSymbolAddress((void**)&enc_h,   g_enc_h);
    cudaGetSymbolAddress((void**)&qt,  g_qt);
    cudaGetSymbolAddress((void**)&kt,  g_kt);
    cudaGetSymbolAddress((void**)&vt,  g_vt);
    cudaGetSymbolAddress((void**)&ctx_h, g_ctx_h);
    cudaGetSymbolAddress((void**)&tmp, g_tmp);
    cudaGetSymbolAddress((void**)&x1,  g_x1);
    cudaGetSymbolAddress((void**)&x1h, g_x1h);
    cudaGetSymbolAddress((void**)&x2,  g_x2);
    cudaGetSymbolAddress((void**)&x2h, g_x2h);
    cudaGetSymbolAddress((void**)&ffn_h, g_ffn_h);
    cudaGetSymbolAddress((void**)&rss, g_rs_self);
    cudaGetSymbolAddress((void**)&rse, g_rs_enc);
    cudaGetSymbolAddress((void**)&wh,  g_wh);

    const int FSM = FL_SMEM_WORDS * 4;
    cudaFuncSetAttribute(gemm_fp16_kernel,  cudaFuncAttributeMaxDynamicSharedMemorySize, GSMB);
    cudaFuncSetAttribute(flash_tf32_kernel, cudaFuncAttributeMaxDynamicSharedMemorySize, FSM);

    float* outx = (float*)d_out;
    float* outa = outx + (size_t)MM * DD;

    // ---- pre-convert weights + input activations to fp16 (one fused kernel) ----
    const int NW = DD * DD;
    const int NF = FFND * DD;
    const int NA = MM * DD;
    CvtJobs jobs;
    jobs.src[0] = saWq; jobs.dst[0] = wh + WOFF_SAQ; jobs.n[0] = NW;
    jobs.src[1] = saWk; jobs.dst[1] = wh + WOFF_SAK; jobs.n[1] = NW;
    jobs.src[2] = saWv; jobs.dst[2] = wh + WOFF_SAV; jobs.n[2] = NW;
    jobs.src[3] = saWo; jobs.dst[3] = wh + WOFF_SAO; jobs.n[3] = NW;
    jobs.src[4] = eaWq; jobs.dst[4] = wh + WOFF_EAQ; jobs.n[4] = NW;
    jobs.src[5] = eaWk; jobs.dst[5] = wh + WOFF_EAK; jobs.n[5] = NW;
    jobs.src[6] = eaWv; jobs.dst[6] = wh + WOFF_EAV; jobs.n[6] = NW;
    jobs.src[7] = eaWo; jobs.dst[7] = wh + WOFF_EAO; jobs.n[7] = NW;
    jobs.src[8] = fc1W; jobs.dst[8] = wh + WOFF_FC1; jobs.n[8] = NF;
    jobs.src[9] = fc2W; jobs.dst[9] = wh + WOFF_FC2; jobs.n[9] = NF;
    jobs.src[10] = state; jobs.dst[10] = state_h; jobs.n[10] = NA;
    jobs.src[11] = enc;   jobs.dst[11] = enc_h;   jobs.n[11] = NA;
    cvt_all_kernel<<<dim3(NF / 1024, 12), 256>>>(jobs);

    expand_mask_kernel<<<(MM + 255) / 256, 256>>>(spad, rss, TT);
    expand_mask_kernel<<<(MM + 255) / 256, 256>>>(epad, rse, SSZ);

    dim3 gP(DD / 128, MM / 256);        // 128 CTAs
    dim3 gF1(FFND / 128, MM / 256);
    dim3 gFl(TT / 128, BB * HH);

    // ---- self-attention ----
    gemm_fp16_kernel<<<gP, 256, GSMB>>>(state_h, wh + WOFF_SAQ, sabq, nullptr, nullptr, qt, nullptr, MM, DD, DD, 0);
    gemm_fp16_kernel<<<gP, 256, GSMB>>>(state_h, wh + WOFF_SAK, sabk, rss,     nullptr, kt, nullptr, MM, DD, DD, 0);
    gemm_fp16_kernel<<<gP, 256, GSMB>>>(state_h, wh + WOFF_SAV, sabv, nullptr, nullptr, vt, nullptr, MM, DD, DD, 0);
    flash_tf32_kernel<<<gFl, 256, FSM>>>(qt, kt, vt, amask, ctx_h, nullptr, 1);
    gemm_fp16_kernel<<<gP, 256, GSMB>>>(ctx_h, wh + WOFF_SAO, sabo, nullptr, tmp, nullptr, nullptr, MM, DD, DD, 0);
    add_ln_kernel<<<MM, 256>>>(tmp, state, ln1g, ln1b, x1, x1h);

    // ---- encoder-decoder attention ----
    gemm_fp16_kernel<<<gP, 256, GSMB>>>(x1h,   wh + WOFF_EAQ, eabq, nullptr, nullptr, qt, nullptr, MM, DD, DD, 0);
    gemm_fp16_kernel<<<gP, 256, GSMB>>>(enc_h, wh + WOFF_EAK, eabk, rse,     nullptr, kt, nullptr, MM, DD, DD, 0);
    gemm_fp16_kernel<<<gP, 256, GSMB>>>(enc_h, wh + WOFF_EAV, eabv, nullptr, nullptr, vt, nullptr, MM, DD, DD, 0);
    flash_tf32_kernel<<<gFl, 256, FSM>>>(qt, kt, vt, nullptr, ctx_h, outa, 0);
    gemm_fp16_kernel<<<gP, 256, GSMB>>>(ctx_h, wh + WOFF_EAO, eabo, nullptr, tmp, nullptr, nullptr, MM, DD, DD, 0);
    add_ln_kernel<<<MM, 256>>>(tmp, x1, ln2g, ln2b, x2, x2h);

    // ---- FFN ----
    gemm_fp16_kernel<<<gF1, 256, GSMB>>>(x2h,   wh + WOFF_FC1, fc1b, nullptr, nullptr, nullptr, ffn_h, MM, FFND, DD, 1);
    gemm_fp16_kernel<<<gP, 256, GSMB>>>(ffn_h, wh + WOFF_FC2, fc2b, nullptr, tmp, nullptr, nullptr, MM, DD, FFND, 0);
    add_ln_kernel<<<MM, 256>>>(tmp, x2, ln3g, ln3b, outx, nullptr);
}

// round 14
// speedup vs baseline: 1.9134x; 1.2402x over previous
#include <cuda_runtime.h>
#include <cuda_fp16.h>
#include <math.h>
#include <stdint.h>

#define TT   1024
#define SSZ  1024
#define BB   4
#define DD   1024
#define HH   16
#define HDD  64
#define FFND 4096
#define MM   (TT*BB)

// ---------------- scratch (device globals; no allocs allowed) ----------------
__device__ __half   g_state_h[MM*DD];
__device__ __half   g_enc_h[MM*DD];
__device__ __half   g_qh[MM*DD];
__device__ __half   g_kh[MM*DD];
__device__ __half   g_vh[MM*DD];
__device__ __half   g_ctx_h[MM*DD];
__device__ float    g_tmp[MM*DD];
__device__ float    g_x1[MM*DD];
__device__ __half   g_x1h[MM*DD];
__device__ float    g_x2[MM*DD];
__device__ __half   g_x2h[MM*DD];
__device__ __half   g_ffn_h[(size_t)MM*FFND];
__device__ float    g_rs_self[MM];
__device__ float    g_rs_enc[MM];
__device__ __half   g_wh[16*1024*1024];

#define WOFF_SAQ  (0*1048576)
#define WOFF_SAK  (1*1048576)
#define WOFF_SAV  (2*1048576)
#define WOFF_SAO  (3*1048576)
#define WOFF_EAQ  (4*1048576)
#define WOFF_EAK  (5*1048576)
#define WOFF_EAV  (6*1048576)
#define WOFF_EAO  (7*1048576)
#define WOFF_FC1  (8*1048576)
#define WOFF_FC2  (12*1048576)

// ---------------- helpers ----------------
__device__ __forceinline__ float block_sum(float v) {
    __shared__ float sh[8];
    __shared__ float res;
    int lane = threadIdx.x & 31, w = threadIdx.x >> 5;
    #pragma unroll
    for (int o = 16; o > 0; o >>= 1) v += __shfl_xor_sync(0xffffffffu, v, o);
    __syncthreads();
    if (lane == 0) sh[w] = v;
    __syncthreads();
    if (threadIdx.x == 0) {
        float t = 0.f;
        #pragma unroll
        for (int i = 0; i < 8; i++) t += sh[i];
        res = t;
    }
    __syncthreads();
    return res;
}

__device__ __forceinline__ void mma_fp16(float* d, const uint32_t* a, uint32_t b0, uint32_t b1) {
    asm volatile(
        "mma.sync.aligned.m16n8k16.row.col.f32.f16.f16.f32 "
        "{%0,%1,%2,%3}, {%4,%5,%6,%7}, {%8,%9}, {%0,%1,%2,%3};"
        : "+f"(d[0]), "+f"(d[1]), "+f"(d[2]), "+f"(d[3])
        : "r"(a[0]), "r"(a[1]), "r"(a[2]), "r"(a[3]), "r"(b0), "r"(b1));
}

__global__ void expand_mask_kernel(const int* __restrict__ mask,
                                   float* __restrict__ rowscale, int L) {
    int r = blockIdx.x * blockDim.x + threadIdx.x;
    if (r < L * BB) {
        int pos = r / BB, b = r % BB;
        rowscale[r] = mask[b * L + pos] ? 0.f : 1.f;
    }
}

// ---------------- fused fp32 -> fp16 conversion over 12 segments ----------------
struct CvtJobs {
    const float* src[12];
    __half*      dst[12];
    int          n[12];
};

__global__ __launch_bounds__(256) void cvt_all_kernel(CvtJobs jobs)
{
    int seg = blockIdx.y;
    int n = jobs.n[seg];
    int i = (blockIdx.x * blockDim.x + threadIdx.x) * 4;
    if (i < n) {
        float4 v = *(const float4*)(jobs.src[seg] + i);
        *(__half2*)(jobs.dst[seg] + i)     = __floats2half2_rn(v.x, v.y);
        *(__half2*)(jobs.dst[seg] + i + 2) = __floats2half2_rn(v.z, v.w);
    }
}

// =====================================================================
// FP16 GEMM (mma.m16n8k16): C = A[M,K] @ W[N,K]^T (+bias, rowscale, relu).
// CTA 256x128, K-chunk 64 halfs. 256 thr, 8 warps 4m x 2n, warp 64x64.
// 2-stage cp.async, SKEW-36-word smem rows. Outputs: C fp32 / Ct16 fp16.
// =====================================================================
#define SKEW 36
#define A_W  (256*SKEW)
#define B_W  (128*SKEW)
#define STG_W (A_W + B_W)
#define GSMB (2*STG_W*4)

__global__ __launch_bounds__(256) void gemm_fp16_kernel(
    const __half* __restrict__ A, const __half* __restrict__ W,
    const float* __restrict__ bias, const float* __restrict__ rowscale,
    float* __restrict__ C, __half* __restrict__ Ct16,
    int M, int N, int K, int relu)
{
    extern __shared__ uint32_t sm[];
    const int tid = threadIdx.x;
    const int lane = tid & 31, warp = tid >> 5;
    const int wm = warp & 3, wn = warp >> 2;
    const int g = lane >> 2, tig = lane & 3;
    const int bx = blockIdx.x, by = blockIdx.y;

    float d[4][8][4];
    #pragma unroll
    for (int mt = 0; mt < 4; mt++)
        #pragma unroll
        for (int nt = 0; nt < 8; nt++)
            #pragma unroll
            for (int i = 0; i < 4; i++) d[mt][nt][i] = 0.f;

    uint32_t smbase = (uint32_t)__cvta_generic_to_shared(sm);
    uint32_t dstA[8], dstB[4];
    const __half *aS[8], *wS[4];
    #pragma unroll
    for (int i = 0; i < 8; i++) {
        int f = tid + (i << 8);
        int r = f >> 3, c16 = f & 7;
        dstA[i] = (uint32_t)(r * SKEW + c16 * 4) * 4;
        aS[i] = A + (size_t)(by * 256 + r) * K + c16 * 8;
    }
    #pragma unroll
    for (int i = 0; i < 4; i++) {
        int f = tid + (i << 8);
        int r = f >> 3, c16 = f & 7;
        dstB[i] = (uint32_t)(A_W + r * SKEW + c16 * 4) * 4;
        wS[i] = W + (size_t)(bx * 128 + r) * K + c16 * 8;
    }

    auto issue = [&](int k0, int stg) {
        uint32_t b = smbase + (uint32_t)stg * (STG_W * 4);
        #pragma unroll
        for (int i = 0; i < 8; i++)
            asm volatile("cp.async.cg.shared.global [%0], [%1], 16;"
                         :: "r"(b + dstA[i]), "l"(aS[i] + k0) : "memory");
        #pragma unroll
        for (int i = 0; i < 4; i++)
            asm volatile("cp.async.cg.shared.global [%0], [%1], 16;"
                         :: "r"(b + dstB[i]), "l"(wS[i] + k0) : "memory");
        asm volatile("cp.async.commit_group;" ::: "memory");
    };

    const int arBase = wm * 64 + g;
    const int bcBase = wn * 64 + g;

    issue(0, 0);
    int stage = 0;
    for (int k0 = 0; k0 < K; k0 += 64) {
        bool nxt = (k0 + 64) < K;
        if (nxt) {
            issue(k0 + 64, stage ^ 1);
            asm volatile("cp.async.wait_group 1;" ::: "memory");
        } else {
            asm volatile("cp.async.wait_group 0;" ::: "memory");
        }
        __syncthreads();

        const uint32_t* Ab = sm + stage * STG_W;
        const uint32_t* Wb = Ab + A_W;
        #pragma unroll
        for (int ks = 0; ks < 4; ks++) {
            int kb = ks * 8;
            uint32_t af[4][4];
            #pragma unroll
            for (int mt = 0; mt < 4; mt++) {
                int ar = arBase + mt * 16;
                af[mt][0] = Ab[ar * SKEW + kb + tig];
                af[mt][1] = Ab[(ar + 8) * SKEW + kb + tig];
                af[mt][2] = Ab[ar * SKEW + kb + tig + 4];
                af[mt][3] = Ab[(ar + 8) * SKEW + kb + tig + 4];
            }
            #pragma unroll
            for (int nt = 0; nt < 8; nt++) {
                int bc = bcBase + nt * 8;
                uint32_t b0 = Wb[bc * SKEW + kb + tig];
                uint32_t b1 = Wb[bc * SKEW + kb + tig + 4];
                #pragma unroll
                for (int mt = 0; mt < 4; mt++)
                    mma_fp16(d[mt][nt], af[mt], b0, b1);
            }
        }
        __syncthreads();
        stage ^= 1;
    }

    #pragma unroll
    for (int mt = 0; mt < 4; mt++) {
        int row0 = by * 256 + wm * 64 + mt * 16 + g;
        float rs0 = rowscale ? rowscale[row0] : 1.f;
        float rs1 = rowscale ? rowscale[row0 + 8] : 1.f;
        #pragma unroll
        for (int nt = 0; nt < 8; nt++) {
            int col = bx * 128 + wn * 64 + nt * 8 + tig * 2;
            float b0 = bias[col], b1 = bias[col + 1];
            float v00 = d[mt][nt][0] * rs0 + b0, v01 = d[mt][nt][1] * rs0 + b1;
            float v10 = d[mt][nt][2] * rs1 + b0, v11 = d[mt][nt][3] * rs1 + b1;
            if (relu) {
                v00 = fmaxf(v00, 0.f); v01 = fmaxf(v01, 0.f);
                v10 = fmaxf(v10, 0.f); v11 = fmaxf(v11, 0.f);
            }
            size_t o0 = (size_t)row0 * N + col;
            size_t o1 = (size_t)(row0 + 8) * N + col;
            if (C) {
                *(float2*)(C + o0) = make_float2(v00, v01);
                *(float2*)(C + o1) = make_float2(v10, v11);
            }
            if (Ct16) {
                *(__half2*)(Ct16 + o0) = __floats2half2_rn(v00, v01);
                *(__half2*)(Ct16 + o1) = __floats2half2_rn(v10, v11);
            }
        }
    }
}

// =====================================================================
// Fused flash attention, full fp16 MMA. Q/K/V fp16 inputs.
// Q,K tiles: [128 rows][64 halfs] stride-36 words. Vt: [64 hd][128 s]
// stride-68 words. P per warp: [16 rows][128 halfs] stride-68 words.
// smem words: Q 4608 | K 4608 | Vt 4352 | P 8*1088 = total 22272 (89KB).
// =====================================================================
#define FQ2 0
#define FK2 4608
#define FV2 9216
#define FP2 13568
#define FL2_WORDS 22272

__global__ __launch_bounds__(256) void flash_fp16_kernel(
    const __half* __restrict__ Q, const __half* __restrict__ Kk,
    const __half* __restrict__ V, const float* __restrict__ mask,
    __half* __restrict__ ctx_h, float* __restrict__ attn, int causal)
{
    extern __shared__ uint32_t sm[];
    uint32_t* Qs = sm + FQ2;
    uint32_t* Ks = sm + FK2;
    uint32_t* Vs = sm + FV2;
    const int tid = threadIdx.x;
    const int lane = tid & 31, warp = tid >> 5;
    const int g = lane >> 2, tig = lane & 3;
    const int bh = blockIdx.y;
    const int bb = bh / HH, h = bh % HH;
    const int t0 = blockIdx.x * 128;
    const int wr0 = warp * 16;
    uint32_t* Pw = sm + FP2 + warp * 1088;

    // load Q tile: 128 rows x 8 chunks (8 halfs) -> 4 per thread
    #pragma unroll
    for (int i = 0; i < 4; i++) {
        int f = tid + (i << 8);
        int r = f >> 3, c16 = f & 7;
        uint4 q4 = *(const uint4*)(Q + ((size_t)(t0 + r) * BB + bb) * DD + h * HDD + c16 * 8);
        *(uint4*)&Qs[r * 36 + c16 * 4] = q4;
    }

    float mA = -1e30f, mB = -1e30f, lA = 0.f, lB = 0.f;
    float o[8][4];
    #pragma unroll
    for (int nt = 0; nt < 8; nt++)
        #pragma unroll
        for (int i = 0; i < 4; i++) o[nt][i] = 0.f;

    const int n_stiles = causal ? (blockIdx.x + 1) : (SSZ / 128);

    for (int is = 0; is < n_stiles; is++) {
        int s0 = is * 128;
        __syncthreads();

        // K tile: like Q
        #pragma unroll
        for (int i = 0; i < 4; i++) {
            int f = tid + (i << 8);
            int r = f >> 3, c16 = f & 7;
            uint4 k4 = *(const uint4*)(Kk + ((size_t)(s0 + r) * BB + bb) * DD + h * HDD + c16 * 8);
            *(uint4*)&Ks[r * 36 + c16 * 4] = k4;
        }
        // V transposed: thread handles s-pair s2 and hd-group hg
        #pragma unroll
        for (int i = 0; i < 2; i++) {
            int f = tid + (i << 8);
            int s2 = f & 63;
            int hg = f >> 6;        // 0..7
            const __half* vr0 = V + ((size_t)(s0 + 2 * s2) * BB + bb) * DD + h * HDD + hg * 8;
            const __half* vr1 = vr0 + (size_t)BB * DD;
            uint4 a4 = *(const uint4*)vr0;
            uint4 b4 = *(const uint4*)vr1;
            const __half* ap = (const __half*)&a4;
            const __half* bp = (const __half*)&b4;
            #pragma unroll
            for (int j = 0; j < 8; j++) {
                __half2 w = __halves2half2(ap[j], bp[j]);
                Vs[(hg * 8 + j) * 68 + s2] = *(uint32_t*)&w;
            }
        }
        __syncthreads();

        // ---- S = Q @ K^T : fp16, 4 k16-steps ----
        float s[16][4];
        #pragma unroll
        for (int nt = 0; nt < 16; nt++)
            #pragma unroll
            for (int i = 0; i < 4; i++) s[nt][i] = 0.f;

        #pragma unroll
        for (int ks = 0; ks < 4; ks++) {
            int kb = ks * 8;
            uint32_t af[4];
            af[0] = Qs[(wr0 + g) * 36 + kb + tig];
            af[1] = Qs[(wr0 + 8 + g) * 36 + kb + tig];
            af[2] = Qs[(wr0 + g) * 36 + kb + tig + 4];
            af[3] = Qs[(wr0 + 8 + g) * 36 + kb + tig + 4];
            #pragma unroll
            for (int nt = 0; nt < 16; nt++) {
                int bc = nt * 8 + g;
                uint32_t b0 = Ks[bc * 36 + kb + tig];
                uint32_t b1 = Ks[bc * 36 + kb + tig + 4];
                mma_fp16(s[nt], af, b0, b1);
            }
        }

        const float scale = 0.125f;
        if (causal && is == blockIdx.x) {
            int tAr = t0 + wr0 + g, tBr = tAr + 8;
            #pragma unroll
            for (int nt = 0; nt < 16; nt++) {
                int c = s0 + nt * 8 + tig * 2;
                s[nt][0] = s[nt][0] * scale + mask[(size_t)tAr * TT + c];
                s[nt][1] = s[nt][1] * scale + mask[(size_t)tAr * TT + c + 1];
                s[nt][2] = s[nt][2] * scale + mask[(size_t)tBr * TT + c];
                s[nt][3] = s[nt][3] * scale + mask[(size_t)tBr * TT + c + 1];
            }
        } else {
            #pragma unroll
            for (int nt = 0; nt < 16; nt++)
                #pragma unroll
                for (int i = 0; i < 4; i++) s[nt][i] *= scale;
        }

        // ---- online softmax (rows g / g+8 within warp tile) ----
        float mtA = -1e30f, mtB = -1e30f;
        #pragma unroll
        for (int nt = 0; nt < 16; nt++) {
            mtA = fmaxf(mtA, fmaxf(s[nt][0], s[nt][1]));
            mtB = fmaxf(mtB, fmaxf(s[nt][2], s[nt][3]));
        }
        mtA = fmaxf(mtA, __shfl_xor_sync(0xffffffffu, mtA, 1));
        mtA = fmaxf(mtA, __shfl_xor_sync(0xffffffffu, mtA, 2));
        mtB = fmaxf(mtB, __shfl_xor_sync(0xffffffffu, mtB, 1));
        mtB = fmaxf(mtB, __shfl_xor_sync(0xffffffffu, mtB, 2));

        float mnA = fmaxf(mA, mtA), mnB = fmaxf(mB, mtB);
        float alA = __expf(mA - mnA), alB = __expf(mB - mnB);
        float rsA = 0.f, rsB = 0.f;
        #pragma unroll
        for (int nt = 0; nt < 16; nt++) {
            s[nt][0] = __expf(s[nt][0] - mnA);
            s[nt][1] = __expf(s[nt][1] - mnA);
            s[nt][2] = __expf(s[nt][2] - mnB);
            s[nt][3] = __expf(s[nt][3] - mnB);
            rsA += s[nt][0] + s[nt][1];
            rsB += s[nt][2] + s[nt][3];
        }
        rsA += __shfl_xor_sync(0xffffffffu, rsA, 1);
        rsA += __shfl_xor_sync(0xffffffffu, rsA, 2);
        rsB += __shfl_xor_sync(0xffffffffu, rsB, 1);
        rsB += __shfl_xor_sync(0xffffffffu, rsB, 2);
        lA = lA * alA + rsA; mA = mnA;
        lB = lB * alB + rsB; mB = mnB;

        #pragma unroll
        for (int nt = 0; nt < 8; nt++) {
            o[nt][0] *= alA; o[nt][1] *= alA;
            o[nt][2] *= alB; o[nt][3] *= alB;
        }

        // ---- P -> warp-private smem as fp16 words ----
        __syncwarp();
        #pragma unroll
        for (int nt = 0; nt < 16; nt++) {
            __half2 wA = __floats2half2_rn(s[nt][0], s[nt][1]);
            __half2 wB = __floats2half2_rn(s[nt][2], s[nt][3]);
            Pw[g * 68 + nt * 4 + tig]       = *(uint32_t*)&wA;
            Pw[(g + 8) * 68 + nt * 4 + tig] = *(uint32_t*)&wB;
        }
        __syncwarp();

        // ---- O += P @ V : fp16, 8 k16-steps ----
        #pragma unroll
        for (int ks = 0; ks < 8; ks++) {
            int kb = ks * 8;
            uint32_t af[4];
            af[0] = Pw[g * 68 + kb + tig];
            af[1] = Pw[(g + 8) * 68 + kb + tig];
            af[2] = Pw[g * 68 + kb + tig + 4];
            af[3] = Pw[(g + 8) * 68 + kb + tig + 4];
            #pragma unroll
            for (int nt = 0; nt < 8; nt++) {
                int bc = nt * 8 + g;
                uint32_t b0 = Vs[bc * 68 + kb + tig];
                uint32_t b1 = Vs[bc * 68 + kb + tig + 4];
                mma_fp16(o[nt], af, b0, b1);
            }
        }
    }

    // ---- epilogue ----
    float invA = 1.f / lA, invB = 1.f / lB;
    int tA = t0 + wr0 + g, tB = tA + 8;
    #pragma unroll
    for (int nt = 0; nt < 8; nt++) {
        int hd = nt * 8 + tig * 2;
        float a0 = o[nt][0] * invA, a1 = o[nt][1] * invA;
        float b0 = o[nt][2] * invB, b1 = o[nt][3] * invB;
        *(__half2*)(ctx_h + ((size_t)tA * BB + bb) * DD + h * HDD + hd) = __floats2half2_rn(a0, a1);
        *(__half2*)(ctx_h + ((size_t)tB * BB + bb) * DD + h * HDD + hd) = __floats2half2_rn(b0, b1);
        if (attn) {
            *(float2*)(attn + (((size_t)h * BB + bb) * TT + tA) * HDD + hd) = make_float2(a0, a1);
            *(float2*)(attn + (((size_t)h * BB + bb) * TT + tB) * HDD + hd) = make_float2(b0, b1);
        }
    }
}

// ---------------- fused residual add + layernorm (optional fp16 dual store)
__global__ __launch_bounds__(256) void add_ln_kernel(
    const float* __restrict__ a, const float* __restrict__ r,
    const float* __restrict__ g, const float* __restrict__ be,
    float* __restrict__ o, __half* __restrict__ oh)
{
    size_t row = blockIdx.x;
    int tid = threadIdx.x;
    float4 va = *(const float4*)(a + row * DD + tid * 4);
    float4 vr = *(const float4*)(r + row * DD + tid * 4);
    float x0 = va.x + vr.x, x1 = va.y + vr.y, x2 = va.z + vr.z, x3 = va.w + vr.w;
    float s  = block_sum(x0 + x1 + x2 + x3);
    float mu = s * (1.f / DD);
    float d0 = x0 - mu, d1 = x1 - mu, d2 = x2 - mu, d3 = x3 - mu;
    float sq = block_sum(d0 * d0 + d1 * d1 + d2 * d2 + d3 * d3);
    float inv = rsqrtf(sq * (1.f / DD) + 1e-5f);
    float4 vg = *(const float4*)(g + tid * 4);
    float4 vb = *(const float4*)(be + tid * 4);
    float4 out;
    out.x = d0 * inv * vg.x + vb.x;
    out.y = d1 * inv * vg.y + vb.y;
    out.z = d2 * inv * vg.z + vb.z;
    out.w = d3 * inv * vg.w + vb.w;
    *(float4*)(o + row * DD + tid * 4) = out;
    if (oh) {
        *(__half2*)(oh + row * DD + tid * 4)     = __floats2half2_rn(out.x, out.y);
        *(__half2*)(oh + row * DD + tid * 4 + 2) = __floats2half2_rn(out.z, out.w);
    }
}

// ---------------- host launch ----------------
extern "C" void kernel_launch(void* const* d_in, const int* in_sizes, int n_in,
                              void* d_out, int out_size)
{
    const float* state = (const float*)d_in[0];
    const float* enc   = (const float*)d_in[1];
    const float* amask = (const float*)d_in[2];
    const int* spad = (const int*)d_in[3];
    const int* epad = (const int*)d_in[4];
    const float *saWq = (const float*)d_in[5],  *sabq = (const float*)d_in[6];
    const float *saWk = (const float*)d_in[7],  *sabk = (const float*)d_in[8];
    const float *saWv = (const float*)d_in[9],  *sabv = (const float*)d_in[10];
    const float *saWo = (const float*)d_in[11], *sabo = (const float*)d_in[12];
    const float *eaWq = (const float*)d_in[13], *eabq = (const float*)d_in[14];
    const float *eaWk = (const float*)d_in[15], *eabk = (const float*)d_in[16];
    const float *eaWv = (const float*)d_in[17], *eabv = (const float*)d_in[18];
    const float *eaWo = (const float*)d_in[19], *eabo = (const float*)d_in[20];
    const float *ln1g = (const float*)d_in[21], *ln1b = (const float*)d_in[22];
    const float *ln2g = (const float*)d_in[23], *ln2b = (const float*)d_in[24];
    const float *ln3g = (const float*)d_in[25], *ln3b = (const float*)d_in[26];
    const float *fc1W = (const float*)d_in[27], *fc1b = (const float*)d_in[28];
    const float *fc2W = (const float*)d_in[29], *fc2b = (const float*)d_in[30];

    __half *state_h, *enc_h, *qh, *kh, *vh, *ctx_h, *x1h, *x2h, *ffn_h, *wh;
    float *tmp, *x1, *x2, *rss, *rse;
    cudaGetSymbolAddress((void**)&state_h, g_state_h);
    cudaGetSymbolAddress((void**)&enc_h,   g_enc_h);
    cudaGetSymbolAddress((void**)&qh,  g_qh);
    cudaGetSymbolAddress((void**)&kh,  g_kh);
    cudaGetSymbolAddress((void**)&vh,  g_vh);
    cudaGetSymbolAddress((void**)&ctx_h, g_ctx_h);
    cudaGetSymbolAddress((void**)&tmp, g_tmp);
    cudaGetSymbolAddress((void**)&x1,  g_x1);
    cudaGetSymbolAddress((void**)&x1h, g_x1h);
    cudaGetSymbolAddress((void**)&x2,  g_x2);
    cudaGetSymbolAddress((void**)&x2h, g_x2h);
    cudaGetSymbolAddress((void**)&ffn_h, g_ffn_h);
    cudaGetSymbolAddress((void**)&rss, g_rs_self);
    cudaGetSymbolAddress((void**)&rse, g_rs_enc);
    cudaGetSymbolAddress((void**)&wh,  g_wh);

    const int FSM = FL2_WORDS * 4;   // 89088
    cudaFuncSetAttribute(gemm_fp16_kernel,  cudaFuncAttributeMaxDynamicSharedMemorySize, GSMB);
    cudaFuncSetAttribute(flash_fp16_kernel, cudaFuncAttributeMaxDynamicSharedMemorySize, FSM);

    float* outx = (float*)d_out;
    float* outa = outx + (size_t)MM * DD;

    // ---- pre-convert weights + input activations to fp16 (one fused kernel) ----
    const int NW = DD * DD;
    const int NF = FFND * DD;
    const int NA = MM * DD;
    CvtJobs jobs;
    jobs.src[0] = saWq; jobs.dst[0] = wh + WOFF_SAQ; jobs.n[0] = NW;
    jobs.src[1] = saWk; jobs.dst[1] = wh + WOFF_SAK; jobs.n[1] = NW;
    jobs.src[2] = saWv; jobs.dst[2] = wh + WOFF_SAV; jobs.n[2] = NW;
    jobs.src[3] = saWo; jobs.dst[3] = wh + WOFF_SAO; jobs.n[3] = NW;
    jobs.src[4] = eaWq; jobs.dst[4] = wh + WOFF_EAQ; jobs.n[4] = NW;
    jobs.src[5] = eaWk; jobs.dst[5] = wh + WOFF_EAK; jobs.n[5] = NW;
    jobs.src[6] = eaWv; jobs.dst[6] = wh + WOFF_EAV; jobs.n[6] = NW;
    jobs.src[7] = eaWo; jobs.dst[7] = wh + WOFF_EAO; jobs.n[7] = NW;
    jobs.src[8] = fc1W; jobs.dst[8] = wh + WOFF_FC1; jobs.n[8] = NF;
    jobs.src[9] = fc2W; jobs.dst[9] = wh + WOFF_FC2; jobs.n[9] = NF;
    jobs.src[10] = state; jobs.dst[10] = state_h; jobs.n[10] = NA;
    jobs.src[11] = enc;   jobs.dst[11] = enc_h;   jobs.n[11] = NA;
    cvt_all_kernel<<<dim3(NF / 1024, 12), 256>>>(jobs);

    expand_mask_kernel<<<(MM + 255) / 256, 256>>>(spad, rss, TT);
    expand_mask_kernel<<<(MM + 255) / 256, 256>>>(epad, rse, SSZ);

    dim3 gP(DD / 128, MM / 256);
    dim3 gF1(FFND / 128, MM / 256);
    dim3 gFl(TT / 128, BB * HH);

    // ---- self-attention ----
    gemm_fp16_kernel<<<gP, 256, GSMB>>>(state_h, wh + WOFF_SAQ, sabq, nullptr, nullptr, qh, MM, DD, DD, 0);
    gemm_fp16_kernel<<<gP, 256, GSMB>>>(state_h, wh + WOFF_SAK, sabk, rss,     nullptr, kh, MM, DD, DD, 0);
    gemm_fp16_kernel<<<gP, 256, GSMB>>>(state_h, wh + WOFF_SAV, sabv, nullptr, nullptr, vh, MM, DD, DD, 0);
    flash_fp16_kernel<<<gFl, 256, FSM>>>(qh, kh, vh, amask, ctx_h, nullptr, 1);
    gemm_fp16_kernel<<<gP, 256, GSMB>>>(ctx_h, wh + WOFF_SAO, sabo, nullptr, tmp, nullptr, MM, DD, DD, 0);
    add_ln_kernel<<<MM, 256>>>(tmp, state, ln1g, ln1b, x1, x1h);

    // ---- encoder-decoder attention ----
    gemm_fp16_kernel<<<gP, 256, GSMB>>>(x1h,   wh + WOFF_EAQ, eabq, nullptr, nullptr, qh, MM, DD, DD, 0);
    gemm_fp16_kernel<<<gP, 256, GSMB>>>(enc_h, wh + WOFF_EAK, eabk, rse,     nullptr, kh, MM, DD, DD, 0);
    gemm_fp16_kernel<<<gP, 256, GSMB>>>(enc_h, wh + WOFF_EAV, eabv, nullptr, nullptr, vh, MM, DD, DD, 0);
    flash_fp16_kernel<<<gFl, 256, FSM>>>(qh, kh, vh, nullptr, ctx_h, outa, 0);
    gemm_fp16_kernel<<<gP, 256, GSMB>>>(ctx_h, wh + WOFF_EAO, eabo, nullptr, tmp, nullptr, MM, DD, DD, 0);
    add_ln_kernel<<<MM, 256>>>(tmp, x1, ln2g, ln2b, x2, x2h);

    // ---- FFN ----
    gemm_fp16_kernel<<<gF1, 256, GSMB>>>(x2h,   wh + WOFF_FC1, fc1b, nullptr, nullptr, ffn_h, MM, FFND, DD, 1);
    gemm_fp16_kernel<<<gP, 256, GSMB>>>(ffn_h, wh + WOFF_FC2, fc2b, nullptr, tmp, nullptr, MM, DD, FFND, 0);
    add_ln_kernel<<<MM, 256>>>(tmp, x2, ln3g, ln3b, outx, nullptr);
}

// round 15
// speedup vs baseline: 1.9897x; 1.0399x over previous
#include <cuda_runtime.h>
#include <cuda_fp16.h>
#include <math.h>
#include <stdint.h>

#define TT   1024
#define SSZ  1024
#define BB   4
#define DD   1024
#define HH   16
#define HDD  64
#define FFND 4096
#define MM   (TT*BB)

// ---------------- scratch (device globals; no allocs allowed) ----------------
__device__ __half   g_state_h[MM*DD];
__device__ __half   g_enc_h[MM*DD];
__device__ __half   g_qh[MM*DD];
__device__ __half   g_kh[MM*DD];
__device__ __half   g_vh[MM*DD];
__device__ __half   g_ctx_h[MM*DD];
__device__ float    g_tmp[MM*DD];
__device__ float    g_x1[MM*DD];
__device__ __half   g_x1h[MM*DD];
__device__ float    g_x2[MM*DD];
__device__ __half   g_x2h[MM*DD];
__device__ __half   g_ffn_h[(size_t)MM*FFND];
__device__ float    g_rs_self[MM];
__device__ float    g_rs_enc[MM];
__device__ __half   g_wh[16*1024*1024];

#define WOFF_SAQ  (0*1048576)
#define WOFF_SAK  (1*1048576)
#define WOFF_SAV  (2*1048576)
#define WOFF_SAO  (3*1048576)
#define WOFF_EAQ  (4*1048576)
#define WOFF_EAK  (5*1048576)
#define WOFF_EAV  (6*1048576)
#define WOFF_EAO  (7*1048576)
#define WOFF_FC1  (8*1048576)
#define WOFF_FC2  (12*1048576)

// ---------------- helpers ----------------
__device__ __forceinline__ float block_sum(float v) {
    __shared__ float sh[8];
    __shared__ float res;
    int lane = threadIdx.x & 31, w = threadIdx.x >> 5;
    #pragma unroll
    for (int o = 16; o > 0; o >>= 1) v += __shfl_xor_sync(0xffffffffu, v, o);
    __syncthreads();
    if (lane == 0) sh[w] = v;
    __syncthreads();
    if (threadIdx.x == 0) {
        float t = 0.f;
        #pragma unroll
        for (int i = 0; i < 8; i++) t += sh[i];
        res = t;
    }
    __syncthreads();
    return res;
}

__device__ __forceinline__ void mma_fp16(float* d, const uint32_t* a, uint32_t b0, uint32_t b1) {
    asm volatile(
        "mma.sync.aligned.m16n8k16.row.col.f32.f16.f16.f32 "
        "{%0,%1,%2,%3}, {%4,%5,%6,%7}, {%8,%9}, {%0,%1,%2,%3};"
        : "+f"(d[0]), "+f"(d[1]), "+f"(d[2]), "+f"(d[3])
        : "r"(a[0]), "r"(a[1]), "r"(a[2]), "r"(a[3]), "r"(b0), "r"(b1));
}

__device__ __forceinline__ void ldsm_x4(uint32_t& r0, uint32_t& r1, uint32_t& r2, uint32_t& r3,
                                        uint32_t addr) {
    asm volatile("ldmatrix.sync.aligned.m8n8.x4.shared.b16 {%0,%1,%2,%3}, [%4];"
                 : "=r"(r0), "=r"(r1), "=r"(r2), "=r"(r3) : "r"(addr));
}

__global__ void expand_mask_kernel(const int* __restrict__ mask,
                                   float* __restrict__ rowscale, int L) {
    int r = blockIdx.x * blockDim.x + threadIdx.x;
    if (r < L * BB) {
        int pos = r / BB, b = r % BB;
        rowscale[r] = mask[b * L + pos] ? 0.f : 1.f;
    }
}

// ---------------- fused fp32 -> fp16 conversion over 12 segments ----------------
struct CvtJobs {
    const float* src[12];
    __half*      dst[12];
    int          n[12];
};

__global__ __launch_bounds__(256) void cvt_all_kernel(CvtJobs jobs)
{
    int seg = blockIdx.y;
    int n = jobs.n[seg];
    int i = (blockIdx.x * blockDim.x + threadIdx.x) * 4;
    if (i < n) {
        float4 v = *(const float4*)(jobs.src[seg] + i);
        *(__half2*)(jobs.dst[seg] + i)     = __floats2half2_rn(v.x, v.y);
        *(__half2*)(jobs.dst[seg] + i + 2) = __floats2half2_rn(v.z, v.w);
    }
}

// =====================================================================
// FP16 GEMM (mma.m16n8k16 + ldmatrix): C = A @ W^T (+bias, rowscale, relu).
// CTA 256x128, K-chunk 64 halfs. 256 thr, 8 warps 4m x 2n, warp 64x64.
// 2-stage cp.async, stride-36-word (144B) smem rows.
// =====================================================================
#define SKEW 36
#define A_W  (256*SKEW)
#define B_W  (128*SKEW)
#define STG_W (A_W + B_W)
#define GSMB (2*STG_W*4)

__global__ __launch_bounds__(256) void gemm_fp16_kernel(
    const __half* __restrict__ A, const __half* __restrict__ W,
    const float* __restrict__ bias, const float* __restrict__ rowscale,
    float* __restrict__ C, __half* __restrict__ Ct16,
    int M, int N, int K, int relu)
{
    extern __shared__ uint32_t sm[];
    const int tid = threadIdx.x;
    const int lane = tid & 31, warp = tid >> 5;
    const int wm = warp & 3, wn = warp >> 2;
    const int g = lane >> 2, tig = lane & 3;
    const int bx = blockIdx.x, by = blockIdx.y;

    float d[4][8][4];
    #pragma unroll
    for (int mt = 0; mt < 4; mt++)
        #pragma unroll
        for (int nt = 0; nt < 8; nt++)
            #pragma unroll
            for (int i = 0; i < 4; i++) d[mt][nt][i] = 0.f;

    uint32_t smbase = (uint32_t)__cvta_generic_to_shared(sm);
    uint32_t dstA[8], dstB[4];
    const __half *aS[8], *wS[4];
    #pragma unroll
    for (int i = 0; i < 8; i++) {
        int f = tid + (i << 8);
        int r = f >> 3, c16 = f & 7;
        dstA[i] = (uint32_t)(r * SKEW + c16 * 4) * 4;
        aS[i] = A + (size_t)(by * 256 + r) * K + c16 * 8;
    }
    #pragma unroll
    for (int i = 0; i < 4; i++) {
        int f = tid + (i << 8);
        int r = f >> 3, c16 = f & 7;
        dstB[i] = (uint32_t)(A_W + r * SKEW + c16 * 4) * 4;
        wS[i] = W + (size_t)(bx * 128 + r) * K + c16 * 8;
    }

    auto issue = [&](int k0, int stg) {
        uint32_t b = smbase + (uint32_t)stg * (STG_W * 4);
        #pragma unroll
        for (int i = 0; i < 8; i++)
            asm volatile("cp.async.cg.shared.global [%0], [%1], 16;"
                         :: "r"(b + dstA[i]), "l"(aS[i] + k0) : "memory");
        #pragma unroll
        for (int i = 0; i < 4; i++)
            asm volatile("cp.async.cg.shared.global [%0], [%1], 16;"
                         :: "r"(b + dstB[i]), "l"(wS[i] + k0) : "memory");
        asm volatile("cp.async.commit_group;" ::: "memory");
    };

    // ldmatrix per-lane byte offsets (stride 144B rows)
    const uint32_t laneA36 = (uint32_t)(((lane & 7) + ((lane >> 3) & 1) * 8) * 144 + (lane >> 4) * 16);
    const uint32_t laneB36 = (uint32_t)((lane & 7) * 144 + ((lane >> 3) & 1) * 16 + (lane >> 4) * 8 * 144);
    const uint32_t aRowB = (uint32_t)(wm * 64) * 144;
    const uint32_t bRowB = (uint32_t)(A_W * 4) + (uint32_t)(wn * 64) * 144;

    issue(0, 0);
    int stage = 0;
    for (int k0 = 0; k0 < K; k0 += 64) {
        bool nxt = (k0 + 64) < K;
        if (nxt) {
            issue(k0 + 64, stage ^ 1);
            asm volatile("cp.async.wait_group 1;" ::: "memory");
        } else {
            asm volatile("cp.async.wait_group 0;" ::: "memory");
        }
        __syncthreads();

        uint32_t abase = smbase + (uint32_t)stage * (STG_W * 4) + aRowB + laneA36;
        uint32_t bbase = smbase + (uint32_t)stage * (STG_W * 4) + bRowB + laneB36;
        #pragma unroll
        for (int ks = 0; ks < 4; ks++) {
            uint32_t kof = ks * 32;
            uint32_t af[4][4];
            #pragma unroll
            for (int mt = 0; mt < 4; mt++)
                ldsm_x4(af[mt][0], af[mt][1], af[mt][2], af[mt][3],
                        abase + (uint32_t)(mt * 16) * 144 + kof);
            #pragma unroll
            for (int ntp = 0; ntp < 4; ntp++) {
                uint32_t b00, b01, b10, b11;
                ldsm_x4(b00, b01, b10, b11, bbase + (uint32_t)(ntp * 16) * 144 + kof);
                #pragma unroll
                for (int mt = 0; mt < 4; mt++) {
                    mma_fp16(d[mt][2 * ntp],     af[mt], b00, b01);
                    mma_fp16(d[mt][2 * ntp + 1], af[mt], b10, b11);
                }
            }
        }
        __syncthreads();
        stage ^= 1;
    }

    #pragma unroll
    for (int mt = 0; mt < 4; mt++) {
        int row0 = by * 256 + wm * 64 + mt * 16 + g;
        float rs0 = rowscale ? rowscale[row0] : 1.f;
        float rs1 = rowscale ? rowscale[row0 + 8] : 1.f;
        #pragma unroll
        for (int nt = 0; nt < 8; nt++) {
            int col = bx * 128 + wn * 64 + nt * 8 + tig * 2;
            float b0 = bias[col], b1 = bias[col + 1];
            float v00 = d[mt][nt][0] * rs0 + b0, v01 = d[mt][nt][1] * rs0 + b1;
            float v10 = d[mt][nt][2] * rs1 + b0, v11 = d[mt][nt][3] * rs1 + b1;
            if (relu) {
                v00 = fmaxf(v00, 0.f); v01 = fmaxf(v01, 0.f);
                v10 = fmaxf(v10, 0.f); v11 = fmaxf(v11, 0.f);
            }
            size_t o0 = (size_t)row0 * N + col;
            size_t o1 = (size_t)(row0 + 8) * N + col;
            if (C) {
                *(float2*)(C + o0) = make_float2(v00, v01);
                *(float2*)(C + o1) = make_float2(v10, v11);
            }
            if (Ct16) {
                *(__half2*)(Ct16 + o0) = __floats2half2_rn(v00, v01);
                *(__half2*)(Ct16 + o1) = __floats2half2_rn(v10, v11);
            }
        }
    }
}

// =====================================================================
// Fused flash attention, fp16 MMA + ldmatrix. Causal CTAs reversed so
// heavy tiles launch first. Q,K: [128][64h] stride-36w; Vt: [64][128h]
// stride-68w; P/warp: [16][128h] stride-68w. smem 22272 words (89KB).
// =====================================================================
#define FQ2 0
#define FK2 4608
#define FV2 9216
#define FP2 13568
#define FL2_WORDS 22272

__global__ __launch_bounds__(256) void flash_fp16_kernel(
    const __half* __restrict__ Q, const __half* __restrict__ Kk,
    const __half* __restrict__ V, const float* __restrict__ mask,
    __half* __restrict__ ctx_h, float* __restrict__ attn, int causal)
{
    extern __shared__ uint32_t sm[];
    uint32_t* Qs = sm + FQ2;
    uint32_t* Ks = sm + FK2;
    uint32_t* Vs = sm + FV2;
    const int tid = threadIdx.x;
    const int lane = tid & 31, warp = tid >> 5;
    const int g = lane >> 2, tig = lane & 3;
    const int bh = blockIdx.y;
    const int bb = bh / HH, h = bh % HH;
    const int tb = causal ? ((int)gridDim.x - 1 - (int)blockIdx.x) : (int)blockIdx.x;
    const int t0 = tb * 128;
    const int wr0 = warp * 16;
    uint32_t* Pw = sm + FP2 + warp * 1088;

    uint32_t smbase = (uint32_t)__cvta_generic_to_shared(sm);
    const uint32_t laneA36 = (uint32_t)(((lane & 7) + ((lane >> 3) & 1) * 8) * 144 + (lane >> 4) * 16);
    const uint32_t laneB36 = (uint32_t)((lane & 7) * 144 + ((lane >> 3) & 1) * 16 + (lane >> 4) * 8 * 144);
    const uint32_t laneA68 = (uint32_t)(((lane & 7) + ((lane >> 3) & 1) * 8) * 272 + (lane >> 4) * 16);
    const uint32_t laneB68 = (uint32_t)((lane & 7) * 272 + ((lane >> 3) & 1) * 16 + (lane >> 4) * 8 * 272);
    const uint32_t qbase = smbase + FQ2 * 4 + (uint32_t)(wr0) * 144 + laneA36;
    const uint32_t kbase = smbase + FK2 * 4 + laneB36;
    const uint32_t vbase = smbase + FV2 * 4 + laneB68;
    const uint32_t pbase = smbase + (FP2 + warp * 1088) * 4 + laneA68;

    // load Q tile
    #pragma unroll
    for (int i = 0; i < 4; i++) {
        int f = tid + (i << 8);
        int r = f >> 3, c16 = f & 7;
        uint4 q4 = *(const uint4*)(Q + ((size_t)(t0 + r) * BB + bb) * DD + h * HDD + c16 * 8);
        *(uint4*)&Qs[r * 36 + c16 * 4] = q4;
    }

    float mA = -1e30f, mB = -1e30f, lA = 0.f, lB = 0.f;
    float o[8][4];
    #pragma unroll
    for (int nt = 0; nt < 8; nt++)
        #pragma unroll
        for (int i = 0; i < 4; i++) o[nt][i] = 0.f;

    const int n_stiles = causal ? (tb + 1) : (SSZ / 128);

    for (int is = 0; is < n_stiles; is++) {
        int s0 = is * 128;
        __syncthreads();

        #pragma unroll
        for (int i = 0; i < 4; i++) {
            int f = tid + (i << 8);
            int r = f >> 3, c16 = f & 7;
            uint4 k4 = *(const uint4*)(Kk + ((size_t)(s0 + r) * BB + bb) * DD + h * HDD + c16 * 8);
            *(uint4*)&Ks[r * 36 + c16 * 4] = k4;
        }
        #pragma unroll
        for (int i = 0; i < 2; i++) {
            int f = tid + (i << 8);
            int s2 = f & 63;
            int hg = f >> 6;
            const __half* vr0 = V + ((size_t)(s0 + 2 * s2) * BB + bb) * DD + h * HDD + hg * 8;
            const __half* vr1 = vr0 + (size_t)BB * DD;
            uint4 a4 = *(const uint4*)vr0;
            uint4 b4 = *(const uint4*)vr1;
            const __half* ap = (const __half*)&a4;
            const __half* bp = (const __half*)&b4;
            #pragma unroll
            for (int j = 0; j < 8; j++) {
                __half2 w = __halves2half2(ap[j], bp[j]);
                Vs[(hg * 8 + j) * 68 + s2] = *(uint32_t*)&w;
            }
        }
        __syncthreads();

        // ---- S = Q @ K^T ----
        float s[16][4];
        #pragma unroll
        for (int nt = 0; nt < 16; nt++)
            #pragma unroll
            for (int i = 0; i < 4; i++) s[nt][i] = 0.f;

        #pragma unroll
        for (int ks = 0; ks < 4; ks++) {
            uint32_t kof = ks * 32;
            uint32_t af[4];
            ldsm_x4(af[0], af[1], af[2], af[3], qbase + kof);
            #pragma unroll
            for (int ntp = 0; ntp < 8; ntp++) {
                uint32_t b00, b01, b10, b11;
                ldsm_x4(b00, b01, b10, b11, kbase + (uint32_t)(ntp * 16) * 144 + kof);
                mma_fp16(s[2 * ntp],     af, b00, b01);
                mma_fp16(s[2 * ntp + 1], af, b10, b11);
            }
        }

        const float scale = 0.125f;
        if (causal && is == tb) {
            int tAr = t0 + wr0 + g, tBr = tAr + 8;
            #pragma unroll
            for (int nt = 0; nt < 16; nt++) {
                int c = s0 + nt * 8 + tig * 2;
                s[nt][0] = s[nt][0] * scale + mask[(size_t)tAr * TT + c];
                s[nt][1] = s[nt][1] * scale + mask[(size_t)tAr * TT + c + 1];
                s[nt][2] = s[nt][2] * scale + mask[(size_t)tBr * TT + c];
                s[nt][3] = s[nt][3] * scale + mask[(size_t)tBr * TT + c + 1];
            }
        } else {
            #pragma unroll
            for (int nt = 0; nt < 16; nt++)
                #pragma unroll
                for (int i = 0; i < 4; i++) s[nt][i] *= scale;
        }

        // ---- online softmax ----
        float mtA = -1e30f, mtB = -1e30f;
        #pragma unroll
        for (int nt = 0; nt < 16; nt++) {
            mtA = fmaxf(mtA, fmaxf(s[nt][0], s[nt][1]));
            mtB = fmaxf(mtB, fmaxf(s[nt][2], s[nt][3]));
        }
        mtA = fmaxf(mtA, __shfl_xor_sync(0xffffffffu, mtA, 1));
        mtA = fmaxf(mtA, __shfl_xor_sync(0xffffffffu, mtA, 2));
        mtB = fmaxf(mtB, __shfl_xor_sync(0xffffffffu, mtB, 1));
        mtB = fmaxf(mtB, __shfl_xor_sync(0xffffffffu, mtB, 2));

        float mnA = fmaxf(mA, mtA), mnB = fmaxf(mB, mtB);
        float alA = __expf(mA - mnA), alB = __expf(mB - mnB);
        float rsA = 0.f, rsB = 0.f;
        #pragma unroll
        for (int nt = 0; nt < 16; nt++) {
            s[nt][0] = __expf(s[nt][0] - mnA);
            s[nt][1] = __expf(s[nt][1] - mnA);
            s[nt][2] = __expf(s[nt][2] - mnB);
            s[nt][3] = __expf(s[nt][3] - mnB);
            rsA += s[nt][0] + s[nt][1];
            rsB += s[nt][2] + s[nt][3];
        }
        rsA += __shfl_xor_sync(0xffffffffu, rsA, 1);
        rsA += __shfl_xor_sync(0xffffffffu, rsA, 2);
        rsB += __shfl_xor_sync(0xffffffffu, rsB, 1);
        rsB += __shfl_xor_sync(0xffffffffu, rsB, 2);
        lA = lA * alA + rsA; mA = mnA;
        lB = lB * alB + rsB; mB = mnB;

        #pragma unroll
        for (int nt = 0; nt < 8; nt++) {
            o[nt][0] *= alA; o[nt][1] *= alA;
            o[nt][2] *= alB; o[nt][3] *= alB;
        }

        // ---- P -> warp-private smem (fp16) ----
        __syncwarp();
        #pragma unroll
        for (int nt = 0; nt < 16; nt++) {
            __half2 wA = __floats2half2_rn(s[nt][0], s[nt][1]);
            __half2 wB = __floats2half2_rn(s[nt][2], s[nt][3]);
            Pw[g * 68 + nt * 4 + tig]       = *(uint32_t*)&wA;
            Pw[(g + 8) * 68 + nt * 4 + tig] = *(uint32_t*)&wB;
        }
        __syncwarp();

        // ---- O += P @ V ----
        #pragma unroll
        for (int ks = 0; ks < 8; ks++) {
            uint32_t kof = ks * 32;
            uint32_t af[4];
            ldsm_x4(af[0], af[1], af[2], af[3], pbase + kof);
            #pragma unroll
            for (int ntp = 0; ntp < 4; ntp++) {
                uint32_t b00, b01, b10, b11;
                ldsm_x4(b00, b01, b10, b11, vbase + (uint32_t)(ntp * 16) * 272 + kof);
                mma_fp16(o[2 * ntp],     af, b00, b01);
                mma_fp16(o[2 * ntp + 1], af, b10, b11);
            }
        }
    }

    // ---- epilogue ----
    float invA = 1.f / lA, invB = 1.f / lB;
    int tA = t0 + wr0 + g, tB = tA + 8;
    #pragma unroll
    for (int nt = 0; nt < 8; nt++) {
        int hd = nt * 8 + tig * 2;
        float a0 = o[nt][0] * invA, a1 = o[nt][1] * invA;
        float b0 = o[nt][2] * invB, b1 = o[nt][3] * invB;
        *(__half2*)(ctx_h + ((size_t)tA * BB + bb) * DD + h * HDD + hd) = __floats2half2_rn(a0, a1);
        *(__half2*)(ctx_h + ((size_t)tB * BB + bb) * DD + h * HDD + hd) = __floats2half2_rn(b0, b1);
        if (attn) {
            *(float2*)(attn + (((size_t)h * BB + bb) * TT + tA) * HDD + hd) = make_float2(a0, a1);
            *(float2*)(attn + (((size_t)h * BB + bb) * TT + tB) * HDD + hd) = make_float2(b0, b1);
        }
    }
}

// ---------------- fused residual add + layernorm (optional fp16 dual store)
__global__ __launch_bounds__(256) void add_ln_kernel(
    const float* __restrict__ a, const float* __restrict__ r,
    const float* __restrict__ g, const float* __restrict__ be,
    float* __restrict__ o, __half* __restrict__ oh)
{
    size_t row = blockIdx.x;
    int tid = threadIdx.x;
    float4 va = *(const float4*)(a + row * DD + tid * 4);
    float4 vr = *(const float4*)(r + row * DD + tid * 4);
    float x0 = va.x + vr.x, x1 = va.y + vr.y, x2 = va.z + vr.z, x3 = va.w + vr.w;
    float s  = block_sum(x0 + x1 + x2 + x3);
    float mu = s * (1.f / DD);
    float d0 = x0 - mu, d1 = x1 - mu, d2 = x2 - mu, d3 = x3 - mu;
    float sq = block_sum(d0 * d0 + d1 * d1 + d2 * d2 + d3 * d3);
    float inv = rsqrtf(sq * (1.f / DD) + 1e-5f);
    float4 vg = *(const float4*)(g + tid * 4);
    float4 vb = *(const float4*)(be + tid * 4);
    float4 out;
    out.x = d0 * inv * vg.x + vb.x;
    out.y = d1 * inv * vg.y + vb.y;
    out.z = d2 * inv * vg.z + vb.z;
    out.w = d3 * inv * vg.w + vb.w;
    *(float4*)(o + row * DD + tid * 4) = out;
    if (oh) {
        *(__half2*)(oh + row * DD + tid * 4)     = __floats2half2_rn(out.x, out.y);
        *(__half2*)(oh + row * DD + tid * 4 + 2) = __floats2half2_rn(out.z, out.w);
    }
}

// ---------------- host launch ----------------
extern "C" void kernel_launch(void* const* d_in, const int* in_sizes, int n_in,
                              void* d_out, int out_size)
{
    const float* state = (const float*)d_in[0];
    const float* enc   = (const float*)d_in[1];
    const float* amask = (const float*)d_in[2];
    const int* spad = (const int*)d_in[3];
    const int* epad = (const int*)d_in[4];
    const float *saWq = (const float*)d_in[5],  *sabq = (const float*)d_in[6];
    const float *saWk = (const float*)d_in[7],  *sabk = (const float*)d_in[8];
    const float *saWv = (const float*)d_in[9],  *sabv = (const float*)d_in[10];
    const float *saWo = (const float*)d_in[11], *sabo = (const float*)d_in[12];
    const float *eaWq = (const float*)d_in[13], *eabq = (const float*)d_in[14];
    const float *eaWk = (const float*)d_in[15], *eabk = (const float*)d_in[16];
    const float *eaWv = (const float*)d_in[17], *eabv = (const float*)d_in[18];
    const float *eaWo = (const float*)d_in[19], *eabo = (const float*)d_in[20];
    const float *ln1g = (const float*)d_in[21], *ln1b = (const float*)d_in[22];
    const float *ln2g = (const float*)d_in[23], *ln2b = (const float*)d_in[24];
    const float *ln3g = (const float*)d_in[25], *ln3b = (const float*)d_in[26];
    const float *fc1W = (const float*)d_in[27], *fc1b = (const float*)d_in[28];
    const float *fc2W = (const float*)d_in[29], *fc2b = (const float*)d_in[30];

    __half *state_h, *enc_h, *qh, *kh, *vh, *ctx_h, *x1h, *x2h, *ffn_h, *wh;
    float *tmp, *x1, *x2, *rss, *rse;
    cudaGetSymbolAddress((void**)&state_h, g_state_h);
    cudaGetSymbolAddress((void**)&enc_h,   g_enc_h);
    cudaGetSymbolAddress((void**)&qh,  g_qh);
    cudaGetSymbolAddress((void**)&kh,  g_kh);
    cudaGetSymbolAddress((void**)&vh,  g_vh);
    cudaGetSymbolAddress((void**)&ctx_h, g_ctx_h);
    cudaGetSymbolAddress((void**)&tmp, g_tmp);
    cudaGetSymbolAddress((void**)&x1,  g_x1);
    cudaGetSymbolAddress((void**)&x1h, g_x1h);
    cudaGetSymbolAddress((void**)&x2,  g_x2);
    cudaGetSymbolAddress((void**)&x2h, g_x2h);
    cudaGetSymbolAddress((void**)&ffn_h, g_ffn_h);
    cudaGetSymbolAddress((void**)&rss, g_rs_self);
    cudaGetSymbolAddress((void**)&rse, g_rs_enc);
    cudaGetSymbolAddress((void**)&wh,  g_wh);

    const int FSM = FL2_WORDS * 4;
    cudaFuncSetAttribute(gemm_fp16_kernel,  cudaFuncAttributeMaxDynamicSharedMemorySize, GSMB);
    cudaFuncSetAttribute(flash_fp16_kernel, cudaFuncAttributeMaxDynamicSharedMemorySize, FSM);

    float* outx = (float*)d_out;
    float* outa = outx + (size_t)MM * DD;

    const int NW = DD * DD;
    const int NF = FFND * DD;
    const int NA = MM * DD;
    CvtJobs jobs;
    jobs.src[0] = saWq; jobs.dst[0] = wh + WOFF_SAQ; jobs.n[0] = NW;
    jobs.src[1] = saWk; jobs.dst[1] = wh + WOFF_SAK; jobs.n[1] = NW;
    jobs.src[2] = saWv; jobs.dst[2] = wh + WOFF_SAV; jobs.n[2] = NW;
    jobs.src[3] = saWo; jobs.dst[3] = wh + WOFF_SAO; jobs.n[3] = NW;
    jobs.src[4] = eaWq; jobs.dst[4] = wh + WOFF_EAQ; jobs.n[4] = NW;
    jobs.src[5] = eaWk; jobs.dst[5] = wh + WOFF_EAK; jobs.n[5] = NW;
    jobs.src[6] = eaWv; jobs.dst[6] = wh + WOFF_EAV; jobs.n[6] = NW;
    jobs.src[7] = eaWo; jobs.dst[7] = wh + WOFF_EAO; jobs.n[7] = NW;
    jobs.src[8] = fc1W; jobs.dst[8] = wh + WOFF_FC1; jobs.n[8] = NF;
    jobs.src[9] = fc2W; jobs.dst[9] = wh + WOFF_FC2; jobs.n[9] = NF;
    jobs.src[10] = state; jobs.dst[10] = state_h; jobs.n[10] = NA;
    jobs.src[11] = enc;   jobs.dst[11] = enc_h;   jobs.n[11] = NA;
    cvt_all_kernel<<<dim3(NF / 1024, 12), 256>>>(jobs);

    expand_mask_kernel<<<(MM + 255) / 256, 256>>>(spad, rss, TT);
    expand_mask_kernel<<<(MM + 255) / 256, 256>>>(epad, rse, SSZ);

    dim3 gP(DD / 128, MM / 256);
    dim3 gF1(FFND / 128, MM / 256);
    dim3 gFl(TT / 128, BB * HH);

    // ---- self-attention ----
    gemm_fp16_kernel<<<gP, 256, GSMB>>>(state_h, wh + WOFF_SAQ, sabq, nullptr, nullptr, qh, MM, DD, DD, 0);
    gemm_fp16_kernel<<<gP, 256, GSMB>>>(state_h, wh + WOFF_SAK, sabk, rss,     nullptr, kh, MM, DD, DD, 0);
    gemm_fp16_kernel<<<gP, 256, GSMB>>>(state_h, wh + WOFF_SAV, sabv, nullptr, nullptr, vh, MM, DD, DD, 0);
    flash_fp16_kernel<<<gFl, 256, FSM>>>(qh, kh, vh, amask, ctx_h, nullptr, 1);
    gemm_fp16_kernel<<<gP, 256, GSMB>>>(ctx_h, wh + WOFF_SAO, sabo, nullptr, tmp, nullptr, MM, DD, DD, 0);
    add_ln_kernel<<<MM, 256>>>(tmp, state, ln1g, ln1b, x1, x1h);

    // ---- encoder-decoder attention ----
    gemm_fp16_kernel<<<gP, 256, GSMB>>>(x1h,   wh + WOFF_EAQ, eabq, nullptr, nullptr, qh, MM, DD, DD, 0);
    gemm_fp16_kernel<<<gP, 256, GSMB>>>(enc_h, wh + WOFF_EAK, eabk, rse,     nullptr, kh, MM, DD, DD, 0);
    gemm_fp16_kernel<<<gP, 256, GSMB>>>(enc_h, wh + WOFF_EAV, eabv, nullptr, nullptr, vh, MM, DD, DD, 0);
    flash_fp16_kernel<<<gFl, 256, FSM>>>(qh, kh, vh, nullptr, ctx_h, outa, 0);
    gemm_fp16_kernel<<<gP, 256, GSMB>>>(ctx_h, wh + WOFF_EAO, eabo, nullptr, tmp, nullptr, MM, DD, DD, 0);
    add_ln_kernel<<<MM, 256>>>(tmp, x1, ln2g, ln2b, x2, x2h);

    // ---- FFN ----
    gemm_fp16_kernel<<<gF1, 256, GSMB>>>(x2h,   wh + WOFF_FC1, fc1b, nullptr, nullptr, ffn_h, MM, FFND, DD, 1);
    gemm_fp16_kernel<<<gP, 256, GSMB>>>(ffn_h, wh + WOFF_FC2, fc2b, nullptr, tmp, nullptr, MM, DD, FFND, 0);
    add_ln_kernel<<<MM, 256>>>(tmp, x2, ln3g, ln3b, outx, nullptr);
}